// round 10
// baseline (speedup 1.0000x reference)
#include <cuda_runtime.h>
#include <cuda_bf16.h>
#include <math.h>
#include <stdint.h>

#define BB 128
#define NB 384
#define TDIM 512
#define DIN 12
#define HH 64
#define DOUT 320
#define BT (BB*TDIM)
#define SLICE_OFF ((size_t)BB*DOUT*TDIM)

// ---------------- static scratch ----------------
__device__ float g_b64_a[(size_t)NB*HH*TDIM];
__device__ float g_b64_b[(size_t)NB*HH*TDIM];
__device__ float g_b64_c[(size_t)NB*HH*TDIM];
__device__ float g_b320_a[(size_t)NB*DOUT*TDIM];
__device__ float g_b320_b[(size_t)NB*DOUT*TDIM];
__device__ float g_b320_c[(size_t)NB*DOUT*TDIM];
__device__ float g_interp[BT*DIN];
__device__ float g_part[(size_t)20*BT*DIN];
__device__ float g_M12[144];
__device__ float g_c12[12];
// converted activations: [bz][ch][544 rows (16 pad | 512 | 16 pad)][64 ci] bf16
__device__ __align__(16) __nv_bfloat16 g_A64h[(size_t)NB*544*64];
__device__ __align__(16) __nv_bfloat16 g_A64l[(size_t)NB*544*64];
__device__ __align__(16) __nv_bfloat16 g_A320h[(size_t)NB*5*544*64];
__device__ __align__(16) __nv_bfloat16 g_A320l[(size_t)NB*5*544*64];
// weight images: 201 blocks of [hl 2][n 64][k 72] bf16 (9216 elems each)
__device__ __align__(16) __nv_bfloat16 g_img[(size_t)201*9216];

// ---------------- helpers ----------------
__device__ __forceinline__ uint32_t s2u(const void* p) {
    uint32_t a;
    asm("{ .reg .u64 t; cvta.to.shared.u64 t, %1; cvt.u32.u64 %0, t; }" : "=r"(a) : "l"(p));
    return a;
}
__device__ __forceinline__ void cp16(uint32_t d, const void* s) {
    asm volatile("cp.async.cg.shared.global [%0], [%1], 16;" :: "r"(d), "l"(s));
}
#define CP_COMMIT() asm volatile("cp.async.commit_group;" ::: "memory")
#define CP_WAIT1()  asm volatile("cp.async.wait_group 1;" ::: "memory")
#define CP_WAIT0()  asm volatile("cp.async.wait_group 0;" ::: "memory")

#define LDSM4(r, a) \
    asm volatile("ldmatrix.sync.aligned.m8n8.x4.shared.b16 {%0,%1,%2,%3}, [%4];" \
        : "=r"((r)[0]), "=r"((r)[1]), "=r"((r)[2]), "=r"((r)[3]) : "r"(a))

__device__ __forceinline__ void mma16816(float* c, const uint32_t* a, const uint32_t* b) {
    asm volatile(
        "mma.sync.aligned.m16n8k16.row.col.f32.bf16.bf16.f32 "
        "{%0,%1,%2,%3}, {%4,%5,%6,%7}, {%8,%9}, {%0,%1,%2,%3};"
        : "+f"(c[0]), "+f"(c[1]), "+f"(c[2]), "+f"(c[3])
        : "r"(a[0]), "r"(a[1]), "r"(a[2]), "r"(a[3]), "r"(b[0]), "r"(b[1]));
}
__device__ __forceinline__ float gelu1(float x) {
    return 0.5f * x * (1.0f + erff(x * 0.7071067811865476f));
}

// ---------------- setup: weight images (hi/lo bf16) + M12 ----------------
__global__ void setup_kernel(
    const float* __restrict__ c01w, const float* __restrict__ c02w,
    const float* __restrict__ c1pw, const float* __restrict__ c11w,
    const float* __restrict__ c12w, const float* __restrict__ dw,
    const float* __restrict__ fc_w, const float* __restrict__ fc_b,
    const float* __restrict__ fcr_w, const float* __restrict__ fcr_b,
    float* __restrict__ M12, float* __restrict__ c12)
{
    const int TOT = 201 * 4096;
    int stride = gridDim.x * 256;
    for (int i = blockIdx.x*256 + threadIdx.x; i < TOT; i += stride) {
        int blk = i >> 12, e = i & 4095;
        int n = e >> 6, k = e & 63;
        float w;
        if (blk < 3) {
            w = c01w[(n*64 + k)*3 + blk];
        } else if (blk < 6) {
            w = c02w[(n*64 + k)*3 + (blk - 3)];
        } else if (blk < 11) {
            int s = blk - 6;
            w = c1pw[(s*64 + n)*64 + k];
        } else if (blk < 26) {
            int r = blk - 11, s = r/3, tap = r%3;
            w = c11w[((s*64 + n)*64 + k)*3 + tap];
        } else if (blk < 101) {
            int r = blk - 26, s = r/15, r2 = r%15, ch = r2/3, tap = r2%3;
            w = c12w[((s*64 + n)*320 + ch*64 + k)*3 + tap];
        } else {
            int r = blk - 101, s = r/5, ch = r%5;
            w = dw[(ch*64 + k)*1280 + s*64 + n];
        }
        size_t base = (size_t)blk * 9216;
        uint32_t idx = (uint32_t)n * 72 + (uint32_t)k;
        __nv_bfloat16 h = __float2bfloat16(w);
        g_img[base + idx] = h;
        g_img[base + 4608 + idx] = __float2bfloat16(w - __bfloat162float(h));
    }
    if (blockIdx.x == 0) {
        int tid = threadIdx.x;
        if (tid < 144) {
            int a = tid / 12, bj = tid % 12;
            float s = 0.f;
            for (int k = 0; k < DOUT; k++) s += fc_w[a*DOUT + k] * fcr_w[k*12 + bj];
            M12[tid] = s;
        } else if (tid < 156) {
            int bj = tid - 144;
            float s = fcr_b[bj];
            for (int k = 0; k < DOUT; k++) s += fc_b[k] * fcr_w[k*12 + bj];
            c12[bj] = s;
        }
    }
}

// ---------------- input projection, all 3 slices ----------------
__global__ void proj_in3_kernel(const float* __restrict__ X1, const float* __restrict__ X2,
                                const float* __restrict__ x1,
                                const float* __restrict__ w, const float* __restrict__ bi,
                                float* __restrict__ out) {
    int bz = blockIdx.y;
    int slice = bz >> 7, b = bz & 127;
    const float* x = (slice == 0) ? X1 : (slice == 1) ? X2 : x1;
    int t = blockIdx.x * 128 + threadIdx.x;
    float xv[DIN];
#pragma unroll
    for (int i = 0; i < DIN; i++) xv[i] = x[(b * TDIM + t) * DIN + i];
    for (int c = 0; c < HH; c++) {
        float s = bi[c];
#pragma unroll
        for (int i = 0; i < DIN; i++) s += xv[i] * w[i * HH + c];
        out[((size_t)bz * HH + c) * TDIM + t] = s;
    }
}

// ------- convert f32 [bz][CH*64][512] -> bf16 hi/lo [bz][ch][544][64] --------
template<bool GELU>
__global__ __launch_bounds__(256) void cvt_kernel(
    const float* __restrict__ in,
    __nv_bfloat16* __restrict__ oh, __nv_bfloat16* __restrict__ ol)
{
    __shared__ float s[64][33];
    int j0 = blockIdx.x * 32;
    int ch = blockIdx.y, CH = gridDim.y;
    size_t bz = blockIdx.z;
    int tid = threadIdx.x;
    const float* src = in + ((size_t)bz * CH + ch) * 64 * TDIM;
    for (int i = tid; i < 64*32; i += 256) {
        int ci = i >> 5, jj = i & 31;
        int t = j0 + jj - 16;
        float v = 0.f;
        if (t >= 0 && t < TDIM) {
            v = src[(size_t)ci*TDIM + t];
            if (GELU) v = gelu1(v);
        }
        s[ci][jj] = v;
    }
    __syncthreads();
    size_t ob = (((size_t)bz * CH + ch) * 544 + j0) * 64;
    for (int i = tid; i < 64*32; i += 256) {
        int jj = i >> 6, ci = i & 63;
        float v = s[ci][jj];
        __nv_bfloat16 h = __float2bfloat16(v);
        oh[ob + (size_t)jj*64 + ci] = h;
        ol[ob + (size_t)jj*64 + ci] = __float2bfloat16(v - __bfloat162float(h));
    }
}

// ---------------- tensor-core conv via mma.sync (split bf16, 3-pass) --------
// 128 threads = 4 warps (2M x 2N), warp tile 64x32 -> 128 B smem per MMA.
// OUTMODE: 0 = channel-major f32; 1 = conv12 (slices 0/1 transposed to d_out,
//          slice 2 channel-major); 2 = dense head (relu + W2 partial to g_part)
template<int CIN, int COUT, int TAPS, int DIL, bool RES, int OUTMODE>
__global__ __launch_bounds__(128) void conv_mma_kernel(
    const __nv_bfloat16* __restrict__ gAh, const __nv_bfloat16* __restrict__ gAl,
    const __nv_bfloat16* __restrict__ img,
    const float* __restrict__ bias, const float* __restrict__ res,
    float* __restrict__ outc, float* __restrict__ outt,
    const float* __restrict__ W2, float* __restrict__ part)
{
    constexpr int CHUNKS = CIN / 64;
    constexpr int NITER = CHUNKS * TAPS;
    extern __shared__ __align__(16) char smem[];
    uint32_t sb = s2u(smem);

    int tid = threadIdx.x, lane = tid & 31, wid = tid >> 5;
    int g = lane >> 2, q = lane & 3;
    int wm = wid >> 1, wn = wid & 1;
    size_t bz = blockIdx.z;
    int t0 = blockIdx.x * 128, sec = blockIdx.y;

    int lrow = lane & 15, lk8 = (lane >> 4) * 8;

    float acc[4][4][4];
#pragma unroll
    for (int a = 0; a < 4; a++)
#pragma unroll
        for (int b = 0; b < 4; b++)
#pragma unroll
            for (int c = 0; c < 4; c++) acc[a][b][c] = 0.f;

    auto loadA = [&](int ch, int slot) {
        size_t rowbase = ((size_t)bz * CHUNKS + ch) * 544 + (16 + t0 - 2);
        for (int i = tid; i < 2112; i += 128) {
            int hl = (i >= 1056) ? 1 : 0;
            int rr = i - hl * 1056;
            int r = rr >> 3, c = rr & 7;
            const __nv_bfloat16* gsrc = (hl ? gAl : gAh) + (rowbase + r) * 64 + c * 8;
            cp16(sb + slot*38016 + hl*19008 + r*144 + c*16, gsrc);
        }
    };
    auto loadB = [&](int it2, int slot) {
        const char* gsrc = (const char*)(img + ((size_t)sec * NITER + it2) * 9216);
        for (int i = tid; i < 1152; i += 128)
            cp16(sb + 76032 + slot*18432 + i*16, gsrc + i*16);
    };

    loadA(0, 0);
    loadB(0, 0);
    CP_COMMIT();

    int it = 0;
    for (int ch = 0; ch < CHUNKS; ch++) {
        for (int tap = 0; tap < TAPS; tap++, it++) {
            __syncthreads();
            if (it + 1 < NITER) {
                loadB(it + 1, (it + 1) & 1);
                if (tap == TAPS - 1 && ch + 1 < CHUNKS) loadA(ch + 1, (ch + 1) & 1);
                CP_COMMIT();
                CP_WAIT1();
            } else {
                CP_WAIT0();
            }
            __syncthreads();
            uint32_t uAh = sb + (ch & 1)*38016;
            uint32_t uB  = sb + 76032 + (it & 1)*18432;
            int rb0 = 2 + (tap - TAPS/2)*DIL + wm*64;
#pragma unroll
            for (int ks = 0; ks < 4; ks++) {
                int kc = ks*16 + lk8;
                uint32_t ah[4][4], al[4][4], bh4[2][4], bl4[2][4];
#pragma unroll
                for (int p = 0; p < 2; p++) {
                    uint32_t baddr = uB + (uint32_t)(((wn*32 + p*16 + lrow)*72 + kc) << 1);
                    LDSM4(bh4[p], baddr);
                    LDSM4(bl4[p], baddr + 9216);
                }
#pragma unroll
                for (int mt = 0; mt < 4; mt++) {
                    uint32_t aaddr = uAh + (uint32_t)((((rb0 + mt*16 + lrow)*72) + kc) << 1);
                    LDSM4(ah[mt], aaddr);
                    LDSM4(al[mt], aaddr + 19008);
                }
#pragma unroll
                for (int mt = 0; mt < 4; mt++)
#pragma unroll
                    for (int nt = 0; nt < 4; nt++) {
                        int p = nt >> 1, sub = nt & 1;
                        uint32_t bhf[2] = {bh4[p][sub], bh4[p][2 + sub]};
                        uint32_t blf[2] = {bl4[p][sub], bl4[p][2 + sub]};
                        mma16816(acc[mt][nt], ah[mt], bhf);
                        mma16816(acc[mt][nt], al[mt], bhf);
                        mma16816(acc[mt][nt], ah[mt], blf);
                    }
            }
        }
    }
    // -------- epilogue --------
    __syncthreads();
    float* stage = (float*)smem;          // [n 64][m 128] at stride 133 (odd)
#pragma unroll
    for (int mt = 0; mt < 4; mt++)
#pragma unroll
        for (int nt = 0; nt < 4; nt++) {
            int m = wm*64 + mt*16 + g;
            int n = wn*32 + nt*8 + q*2;
            stage[n*133 + m]         = acc[mt][nt][0];
            stage[(n+1)*133 + m]     = acc[mt][nt][1];
            stage[n*133 + m + 8]     = acc[mt][nt][2];
            stage[(n+1)*133 + m + 8] = acc[mt][nt][3];
        }
    __syncthreads();

    if (OUTMODE == 2) {
        float* sW2 = (float*)(smem + 76032);   // 64*12 f32
        float* sB1 = sW2 + 64*12;              // 64 f32
        for (int i = tid; i < 64*12; i += 128)
            sW2[i] = __ldg(W2 + (sec*64 + i/12)*12 + (i%12));
        if (tid < 64) sB1[tid] = __ldg(bias + sec*64 + tid);
        __syncthreads();
        for (int i = tid; i < 128*12; i += 128) {
            int tl = i / 12, o = i % 12;
            float s = 0.f;
#pragma unroll 8
            for (int cl = 0; cl < 64; cl++) {
                float v = stage[cl*133 + tl] + sB1[cl];
                v = v > 0.f ? v : 0.f;
                s += v * sW2[cl*12 + o];
            }
            part[((size_t)sec*BT + bz*TDIM + t0 + tl)*12 + o] = s;
        }
        return;
    }

    // add bias (+res) in channel-major order (coalesced res/gmem)
    bool transposed = (OUTMODE == 1) && (bz < 256);
    for (int i = tid; i < 64*128; i += 128) {
        int cl = i >> 7, tl = i & 127;
        int co = sec*64 + cl;
        float v = stage[cl*133 + tl] + __ldg(bias + co);
        if (RES) v += __ldg(res + ((size_t)bz*COUT + co)*TDIM + t0 + tl);
        if (!transposed) {
            outc[((size_t)bz*COUT + co)*TDIM + t0 + tl] = v;
        } else {
            stage[cl*133 + tl] = v;
        }
    }
    if (transposed) {
        __syncthreads();
        int slice = (int)(bz >> 7), b = (int)(bz & 127);
        float* dst = outt + (((size_t)slice*BT) + (size_t)b*TDIM + t0)*DOUT + sec*64;
        for (int i = tid; i < 128*64; i += 128) {
            int tl = i >> 6, cl = i & 63;
            dst[(size_t)tl*DOUT + cl] = stage[cl*133 + tl];
        }
    }
}

// ---- reduce 20 dense partials + b2 -> interp ----
__global__ void reduce_kernel(const float* __restrict__ part,
                              const float* __restrict__ b2,
                              float* __restrict__ interp) {
    int i = blockIdx.x * 256 + threadIdx.x;
    if (i >= BT * DIN) return;
    float s = b2[i % 12];
#pragma unroll
    for (int sec = 0; sec < 20; sec++) s += part[(size_t)sec*BT*DIN + i];
    interp[i] = s;
}

// ---- finale: outputs + masks + passthrough (GRU provably dead: mask1==1) ---
__global__ void finale_kernel(const float* __restrict__ interp,
                              const float* __restrict__ M12, const float* __restrict__ c12,
                              const float* __restrict__ x1, const float* __restrict__ x2,
                              float* __restrict__ o1, float* __restrict__ o2,
                              float* __restrict__ om1, float* __restrict__ om2,
                              float* __restrict__ ox1, float* __restrict__ ox2) {
    int r = blockIdx.x * blockDim.x + threadIdx.x;
    if (r >= BT) return;
    float xv[12];
#pragma unroll
    for (int i = 0; i < 12; i++) xv[i] = interp[r * 12 + i];
#pragma unroll
    for (int j = 0; j < 12; j++) {
        float s = c12[j];
#pragma unroll
        for (int i = 0; i < 12; i++) s += xv[i] * M12[i * 12 + j];
        o1[r * 12 + j] = s;
        o2[r * 12 + j] = s;
    }
#pragma unroll
    for (int j = 0; j < 12; j++) {
        float a = x1[r * 12 + j], b = x2[r * 12 + j];
        om1[r * 12 + j] = (a != 0.f) ? 1.f : 0.f;
        om2[r * 12 + j] = (b != 0.f) ? 1.f : 0.f;
        ox1[r * 12 + j] = a;
        ox2[r * 12 + j] = b;
    }
}

// ---------------- host ----------------
#define SMEM_MMA 112896

extern "C" void kernel_launch(void* const* d_in, const int* in_sizes, int n_in,
                              void* d_out, int out_size) {
    const float* x1 = (const float*)d_in[0];
    const float* x2 = (const float*)d_in[1];
    const float* X1 = (const float*)d_in[2];
    const float* X2 = (const float*)d_in[3];
    const float* w_in = (const float*)d_in[5];
    const float* b_in = (const float*)d_in[6];
    const float* c0_1_w = (const float*)d_in[7];
    const float* c0_1_b = (const float*)d_in[8];
    const float* c0_2_w = (const float*)d_in[9];
    const float* c0_2_b = (const float*)d_in[10];
    const float* c1_p_w = (const float*)d_in[11];
    const float* c1_p_b = (const float*)d_in[12];
    const float* c1_1_w = (const float*)d_in[13];
    const float* c1_1_b = (const float*)d_in[14];
    const float* c1_2_w = (const float*)d_in[15];
    const float* c1_2_b = (const float*)d_in[16];
    const float* ih_dense_w = (const float*)d_in[17];
    const float* ih_dense_b = (const float*)d_in[18];
    const float* ih_proj_w = (const float*)d_in[19];
    const float* ih_proj_b = (const float*)d_in[20];
    const float* fc_w = (const float*)d_in[21];
    const float* fc_b = (const float*)d_in[22];
    const float* fcr_w = (const float*)d_in[29];
    const float* fcr_b = (const float*)d_in[30];

    float *b64a, *b64b, *b64c, *b320a, *b320b, *b320c, *interp, *part, *M12, *c12;
    __nv_bfloat16 *A64h, *A64l, *A320h, *A320l, *img;
    cudaGetSymbolAddress((void**)&b64a, g_b64_a);
    cudaGetSymbolAddress((void**)&b64b, g_b64_b);
    cudaGetSymbolAddress((void**)&b64c, g_b64_c);
    cudaGetSymbolAddress((void**)&b320a, g_b320_a);
    cudaGetSymbolAddress((void**)&b320b, g_b320_b);
    cudaGetSymbolAddress((void**)&b320c, g_b320_c);
    cudaGetSymbolAddress((void**)&interp, g_interp);
    cudaGetSymbolAddress((void**)&part, g_part);
    cudaGetSymbolAddress((void**)&M12, g_M12);
    cudaGetSymbolAddress((void**)&c12, g_c12);
    cudaGetSymbolAddress((void**)&A64h, g_A64h);
    cudaGetSymbolAddress((void**)&A64l, g_A64l);
    cudaGetSymbolAddress((void**)&A320h, g_A320h);
    cudaGetSymbolAddress((void**)&A320l, g_A320l);
    cudaGetSymbolAddress((void**)&img, g_img);

    cudaFuncSetAttribute(conv_mma_kernel<64,64,3,1,false,0>,
                         cudaFuncAttributeMaxDynamicSharedMemorySize, SMEM_MMA);
    cudaFuncSetAttribute(conv_mma_kernel<64,64,3,1,true,0>,
                         cudaFuncAttributeMaxDynamicSharedMemorySize, SMEM_MMA);
    cudaFuncSetAttribute(conv_mma_kernel<64,320,1,1,false,0>,
                         cudaFuncAttributeMaxDynamicSharedMemorySize, SMEM_MMA);
    cudaFuncSetAttribute(conv_mma_kernel<64,320,3,2,false,0>,
                         cudaFuncAttributeMaxDynamicSharedMemorySize, SMEM_MMA);
    cudaFuncSetAttribute(conv_mma_kernel<320,320,3,2,true,1>,
                         cudaFuncAttributeMaxDynamicSharedMemorySize, SMEM_MMA);
    cudaFuncSetAttribute(conv_mma_kernel<320,1280,1,1,false,2>,
                         cudaFuncAttributeMaxDynamicSharedMemorySize, SMEM_MMA);

    float* out = (float*)d_out;
    float* o_o1  = out + 2 * (size_t)BT * DOUT;
    float* o_o2  = o_o1 + (size_t)BT * DIN;
    float* o_m1  = o_o2 + (size_t)BT * DIN;
    float* o_m2  = o_m1 + (size_t)BT * DIN;
    float* o_x1  = o_m2 + (size_t)BT * DIN;
    float* o_x2  = o_x1 + (size_t)BT * DIN;

    setup_kernel<<<3216, 256>>>(c0_1_w, c0_2_w, c1_p_w, c1_1_w, c1_2_w, ih_dense_w,
                                fc_w, fc_b, fcr_w, fcr_b, M12, c12);
    proj_in3_kernel<<<dim3(TDIM / 128, NB), 128>>>(X1, X2, x1, w_in, b_in, b64a);

    dim3 cg64(17, 1, NB), cg320(17, 5, NB), cg320d(17, 5, BB);
    // block0
    cvt_kernel<true><<<cg64, 256>>>(b64a, A64h, A64l);
    conv_mma_kernel<64,64,3,1,false,0><<<dim3(4,1,NB), 128, SMEM_MMA>>>(
        A64h, A64l, img, c0_1_b, nullptr, b64b, nullptr, nullptr, nullptr);
    cvt_kernel<true><<<cg64, 256>>>(b64b, A64h, A64l);
    conv_mma_kernel<64,64,3,1,true,0><<<dim3(4,1,NB), 128, SMEM_MMA>>>(
        A64h, A64l, img + (size_t)3*9216, c0_2_b, b64a, b64c, nullptr, nullptr, nullptr);
    // block1
    cvt_kernel<false><<<cg64, 256>>>(b64c, A64h, A64l);
    conv_mma_kernel<64,320,1,1,false,0><<<dim3(4,5,NB), 128, SMEM_MMA>>>(
        A64h, A64l, img + (size_t)6*9216, c1_p_b, nullptr, b320a, nullptr, nullptr, nullptr);
    cvt_kernel<true><<<cg64, 256>>>(b64c, A64h, A64l);
    conv_mma_kernel<64,320,3,2,false,0><<<dim3(4,5,NB), 128, SMEM_MMA>>>(
        A64h, A64l, img + (size_t)11*9216, c1_1_b, nullptr, b320b, nullptr, nullptr, nullptr);
    cvt_kernel<true><<<cg320, 256>>>(b320b, A320h, A320l);
    conv_mma_kernel<320,320,3,2,true,1><<<dim3(4,5,NB), 128, SMEM_MMA>>>(
        A320h, A320l, img + (size_t)26*9216, c1_2_b, b320a, b320c, out, nullptr, nullptr);
    // dense head on slice 2 (dense2 fused into epilogue -> partials)
    cvt_kernel<false><<<cg320d, 256>>>(b320c + 2*SLICE_OFF, A320h, A320l);
    conv_mma_kernel<320,1280,1,1,false,2><<<dim3(4,20,BB), 128, SMEM_MMA>>>(
        A320h, A320l, img + (size_t)101*9216, ih_dense_b, nullptr,
        nullptr, nullptr, ih_proj_w, part);
    reduce_kernel<<<(BT*DIN + 255)/256, 256>>>(part, ih_proj_b, interp);
    finale_kernel<<<(BT + 127) / 128, 128>>>(interp, M12, c12, x1, x2,
                                             o_o1, o_o2, o_m1, o_m2, o_x1, o_x2);
}

// round 11
// speedup vs baseline: 1.7455x; 1.7455x over previous
#include <cuda_runtime.h>
#include <cuda_bf16.h>
#include <math.h>
#include <stdint.h>

#define BB 128
#define NB 384
#define TDIM 512
#define DIN 12
#define HH 64
#define DOUT 320
#define BT (BB*TDIM)
#define SLICE_OFF ((size_t)BB*DOUT*TDIM)

// ---------------- static scratch ----------------
__device__ float g_b64_a[(size_t)NB*HH*TDIM];
__device__ float g_b64_b[(size_t)NB*HH*TDIM];
__device__ float g_b64_c[(size_t)NB*HH*TDIM];
__device__ float g_b320_a[(size_t)NB*DOUT*TDIM];
__device__ float g_b320_b[(size_t)NB*DOUT*TDIM];
__device__ float g_b320_c[(size_t)NB*DOUT*TDIM];
__device__ float g_interp[BT*DIN];
__device__ float g_part[(size_t)20*BT*DIN];
__device__ float g_M12[144];
__device__ float g_c12[12];
// converted activations: [bz][ch][544 rows (16 pad | 512 | 16 pad)][64 ci] bf16
__device__ __align__(16) __nv_bfloat16 g_A64h[(size_t)NB*544*64];
__device__ __align__(16) __nv_bfloat16 g_A64l[(size_t)NB*544*64];
__device__ __align__(16) __nv_bfloat16 g_A320h[(size_t)NB*5*544*64];
__device__ __align__(16) __nv_bfloat16 g_A320l[(size_t)NB*5*544*64];
// weight images: 201 blocks of [hl 2][n 64][k 72] bf16 (9216 elems each)
__device__ __align__(16) __nv_bfloat16 g_img[(size_t)201*9216];

// ---------------- helpers ----------------
__device__ __forceinline__ uint32_t s2u(const void* p) {
    uint32_t a;
    asm("{ .reg .u64 t; cvta.to.shared.u64 t, %1; cvt.u32.u64 %0, t; }" : "=r"(a) : "l"(p));
    return a;
}
__device__ __forceinline__ void cp16(uint32_t d, const void* s) {
    asm volatile("cp.async.cg.shared.global [%0], [%1], 16;" :: "r"(d), "l"(s));
}
#define CP_COMMIT() asm volatile("cp.async.commit_group;" ::: "memory")
#define CP_WAIT1()  asm volatile("cp.async.wait_group 1;" ::: "memory")
#define CP_WAIT0()  asm volatile("cp.async.wait_group 0;" ::: "memory")

__device__ __forceinline__ void mma16816(float* c, const uint32_t* a, const uint32_t* b) {
    asm volatile(
        "mma.sync.aligned.m16n8k16.row.col.f32.bf16.bf16.f32 "
        "{%0,%1,%2,%3}, {%4,%5,%6,%7}, {%8,%9}, {%0,%1,%2,%3};"
        : "+f"(c[0]), "+f"(c[1]), "+f"(c[2]), "+f"(c[3])
        : "r"(a[0]), "r"(a[1]), "r"(a[2]), "r"(a[3]), "r"(b[0]), "r"(b[1]));
}
__device__ __forceinline__ float gelu1(float x) {
    return 0.5f * x * (1.0f + erff(x * 0.7071067811865476f));
}

// ---------------- setup: weight images (hi/lo bf16) + M12 ----------------
__global__ void setup_kernel(
    const float* __restrict__ c01w, const float* __restrict__ c02w,
    const float* __restrict__ c1pw, const float* __restrict__ c11w,
    const float* __restrict__ c12w, const float* __restrict__ dw,
    const float* __restrict__ fc_w, const float* __restrict__ fc_b,
    const float* __restrict__ fcr_w, const float* __restrict__ fcr_b,
    float* __restrict__ M12, float* __restrict__ c12)
{
    const int TOT = 201 * 4096;
    int stride = gridDim.x * 256;
    for (int i = blockIdx.x*256 + threadIdx.x; i < TOT; i += stride) {
        int blk = i >> 12, e = i & 4095;
        int n = e >> 6, k = e & 63;
        float w;
        if (blk < 3) {
            w = c01w[(n*64 + k)*3 + blk];
        } else if (blk < 6) {
            w = c02w[(n*64 + k)*3 + (blk - 3)];
        } else if (blk < 11) {
            int s = blk - 6;
            w = c1pw[(s*64 + n)*64 + k];
        } else if (blk < 26) {
            int r = blk - 11, s = r/3, tap = r%3;
            w = c11w[((s*64 + n)*64 + k)*3 + tap];
        } else if (blk < 101) {
            int r = blk - 26, s = r/15, r2 = r%15, ch = r2/3, tap = r2%3;
            w = c12w[((s*64 + n)*320 + ch*64 + k)*3 + tap];
        } else {
            int r = blk - 101, s = r/5, ch = r%5;
            w = dw[(ch*64 + k)*1280 + s*64 + n];
        }
        size_t base = (size_t)blk * 9216;
        uint32_t idx = (uint32_t)n * 72 + (uint32_t)k;
        __nv_bfloat16 h = __float2bfloat16(w);
        g_img[base + idx] = h;
        g_img[base + 4608 + idx] = __float2bfloat16(w - __bfloat162float(h));
    }
    if (blockIdx.x == 0) {
        int tid = threadIdx.x;
        if (tid < 144) {
            int a = tid / 12, bj = tid % 12;
            float s = 0.f;
            for (int k = 0; k < DOUT; k++) s += fc_w[a*DOUT + k] * fcr_w[k*12 + bj];
            M12[tid] = s;
        } else if (tid < 156) {
            int bj = tid - 144;
            float s = fcr_b[bj];
            for (int k = 0; k < DOUT; k++) s += fc_b[k] * fcr_w[k*12 + bj];
            c12[bj] = s;
        }
    }
}

// ---------------- input projection, all 3 slices ----------------
__global__ void proj_in3_kernel(const float* __restrict__ X1, const float* __restrict__ X2,
                                const float* __restrict__ x1,
                                const float* __restrict__ w, const float* __restrict__ bi,
                                float* __restrict__ out) {
    int bz = blockIdx.y;
    int slice = bz >> 7, b = bz & 127;
    const float* x = (slice == 0) ? X1 : (slice == 1) ? X2 : x1;
    int t = blockIdx.x * 128 + threadIdx.x;
    float xv[DIN];
#pragma unroll
    for (int i = 0; i < DIN; i++) xv[i] = x[(b * TDIM + t) * DIN + i];
    for (int c = 0; c < HH; c++) {
        float s = bi[c];
#pragma unroll
        for (int i = 0; i < DIN; i++) s += xv[i] * w[i * HH + c];
        out[((size_t)bz * HH + c) * TDIM + t] = s;
    }
}

// ------- convert f32 [bz][CH*64][512] -> bf16 hi/lo [bz][ch][544][64] --------
template<bool GELU>
__global__ __launch_bounds__(256) void cvt_kernel(
    const float* __restrict__ in,
    __nv_bfloat16* __restrict__ oh, __nv_bfloat16* __restrict__ ol)
{
    __shared__ float s[64][33];
    int j0 = blockIdx.x * 32;
    int ch = blockIdx.y, CH = gridDim.y;
    size_t bz = blockIdx.z;
    int tid = threadIdx.x;
    const float* src = in + ((size_t)bz * CH + ch) * 64 * TDIM;
    for (int i = tid; i < 64*32; i += 256) {
        int ci = i >> 5, jj = i & 31;
        int t = j0 + jj - 16;
        float v = 0.f;
        if (t >= 0 && t < TDIM) {
            v = src[(size_t)ci*TDIM + t];
            if (GELU) v = gelu1(v);
        }
        s[ci][jj] = v;
    }
    __syncthreads();
    size_t ob = (((size_t)bz * CH + ch) * 544 + j0) * 64;
    for (int i = tid; i < 64*32; i += 256) {
        int jj = i >> 6, ci = i & 63;
        float v = s[ci][jj];
        __nv_bfloat16 h = __float2bfloat16(v);
        oh[ob + (size_t)jj*64 + ci] = h;
        ol[ob + (size_t)jj*64 + ci] = __float2bfloat16(v - __bfloat162float(h));
    }
}

// ---------------- tensor-core conv via mma.sync (split bf16, 3-pass) --------
// 256 thr = 8 warps (2M x 4N), warp tile 64x16. Single A buffer + double B
// buffer -> 74880 B smem -> 3 CTAs/SM.
// OUTMODE: 0 = channel-major f32; 1 = conv12 (slices 0/1 transposed to d_out,
//          slice 2 channel-major); 2 = dense head (relu + W2 partial to g_part)
template<int CIN, int COUT, int TAPS, int DIL, bool RES, int OUTMODE>
__global__ __launch_bounds__(256) void conv_mma_kernel(
    const __nv_bfloat16* __restrict__ gAh, const __nv_bfloat16* __restrict__ gAl,
    const __nv_bfloat16* __restrict__ img,
    const float* __restrict__ bias, const float* __restrict__ res,
    float* __restrict__ outc, float* __restrict__ outt,
    const float* __restrict__ W2, float* __restrict__ part)
{
    constexpr int CHUNKS = CIN / 64;
    constexpr int NITER = CHUNKS * TAPS;
    extern __shared__ __align__(16) char smem[];
    uint32_t sb = s2u(smem);

    int tid = threadIdx.x, lane = tid & 31, wid = tid >> 5;
    int g = lane >> 2, q = lane & 3;
    int wm = wid >> 2, wn = wid & 3;
    size_t bz = blockIdx.z;
    int t0 = blockIdx.x * 128, sec = blockIdx.y;

    float acc[4][2][4];
#pragma unroll
    for (int a = 0; a < 4; a++)
#pragma unroll
        for (int b = 0; b < 2; b++)
#pragma unroll
            for (int c = 0; c < 4; c++) acc[a][b][c] = 0.f;

    // A: [0, 38016) single buffer (hi 19008 | lo 19008)
    // B: [38016, 74880) two buffers of 18432
    auto loadA = [&](int ch) {
        size_t rowbase = ((size_t)bz * CHUNKS + ch) * 544 + (16 + t0 - 2);
        for (int i = tid; i < 2112; i += 256) {
            int hl = (i >= 1056) ? 1 : 0;
            int rr = i - hl * 1056;
            int r = rr >> 3, c = rr & 7;
            const __nv_bfloat16* gsrc = (hl ? gAl : gAh) + (rowbase + r) * 64 + c * 8;
            cp16(sb + hl*19008 + r*144 + c*16, gsrc);
        }
    };
    auto loadB = [&](int it2, int slot) {
        const char* gsrc = (const char*)(img + ((size_t)sec * NITER + it2) * 9216);
        for (int i = tid; i < 1152; i += 256)
            cp16(sb + 38016 + slot*18432 + i*16, gsrc + i*16);
    };

    loadB(0, 0);
    CP_COMMIT();

    int it = 0;
    for (int ch = 0; ch < CHUNKS; ch++) {
        for (int tap = 0; tap < TAPS; tap++, it++) {
            __syncthreads();     // prior compute done: A buffer / B slot safe
            if (tap == 0) { loadA(ch); CP_COMMIT(); }
            if (it + 1 < NITER) {
                loadB(it + 1, (it + 1) & 1);
                CP_COMMIT();
                CP_WAIT1();      // A (if any) + B(it) complete; B(it+1) in flight
            } else {
                CP_WAIT0();
            }
            __syncthreads();
            const __nv_bfloat16* sAh = (const __nv_bfloat16*)smem;
            const __nv_bfloat16* sAl = sAh + 9504;
            const __nv_bfloat16* sBh = (const __nv_bfloat16*)(smem + 38016 + (it & 1)*18432);
            const __nv_bfloat16* sBl = sBh + 4608;
            int rb = 2 + (tap - TAPS/2)*DIL + wm*64 + g;
#pragma unroll
            for (int ks = 0; ks < 4; ks++) {
                int kc = ks*16 + q*2;
                uint32_t ah[4][4], al[4][4], bh[2][2], bl[2][2];
#pragma unroll
                for (int mt = 0; mt < 4; mt++) {
                    int base = (rb + mt*16)*72 + kc;
                    ah[mt][0] = *(const uint32_t*)(sAh + base);
                    ah[mt][1] = *(const uint32_t*)(sAh + base + 8*72);
                    ah[mt][2] = *(const uint32_t*)(sAh + base + 8);
                    ah[mt][3] = *(const uint32_t*)(sAh + base + 8*72 + 8);
                    al[mt][0] = *(const uint32_t*)(sAl + base);
                    al[mt][1] = *(const uint32_t*)(sAl + base + 8*72);
                    al[mt][2] = *(const uint32_t*)(sAl + base + 8);
                    al[mt][3] = *(const uint32_t*)(sAl + base + 8*72 + 8);
                }
#pragma unroll
                for (int nt = 0; nt < 2; nt++) {
                    int nb = (wn*16 + nt*8 + g)*72 + kc;
                    bh[nt][0] = *(const uint32_t*)(sBh + nb);
                    bh[nt][1] = *(const uint32_t*)(sBh + nb + 8);
                    bl[nt][0] = *(const uint32_t*)(sBl + nb);
                    bl[nt][1] = *(const uint32_t*)(sBl + nb + 8);
                }
#pragma unroll
                for (int mt = 0; mt < 4; mt++)
#pragma unroll
                    for (int nt = 0; nt < 2; nt++) {
                        mma16816(acc[mt][nt], ah[mt], bh[nt]);
                        mma16816(acc[mt][nt], al[mt], bh[nt]);
                        mma16816(acc[mt][nt], ah[mt], bl[nt]);
                    }
            }
        }
    }
    // -------- epilogue --------
    __syncthreads();
    float* stage = (float*)smem;          // [n 64][m 128] at stride 133 (odd)
#pragma unroll
    for (int mt = 0; mt < 4; mt++)
#pragma unroll
        for (int nt = 0; nt < 2; nt++) {
            int m = wm*64 + mt*16 + g;
            int n = wn*16 + nt*8 + q*2;
            stage[n*133 + m]         = acc[mt][nt][0];
            stage[(n+1)*133 + m]     = acc[mt][nt][1];
            stage[n*133 + m + 8]     = acc[mt][nt][2];
            stage[(n+1)*133 + m + 8] = acc[mt][nt][3];
        }
    __syncthreads();

    if (OUTMODE == 2) {
        float* sW2 = (float*)(smem + 34048);   // 64*12 f32
        float* sB1 = sW2 + 64*12;              // 64 f32
        for (int i = tid; i < 64*12; i += 256)
            sW2[i] = __ldg(W2 + (sec*64 + i/12)*12 + (i%12));
        if (tid < 64) sB1[tid] = __ldg(bias + sec*64 + tid);
        __syncthreads();
        for (int i = tid; i < 128*12; i += 256) {
            int tl = i / 12, o = i % 12;
            float s = 0.f;
#pragma unroll 8
            for (int cl = 0; cl < 64; cl++) {
                float v = stage[cl*133 + tl] + sB1[cl];
                v = v > 0.f ? v : 0.f;
                s += v * sW2[cl*12 + o];
            }
            part[((size_t)sec*BT + bz*TDIM + t0 + tl)*12 + o] = s;
        }
        return;
    }

    // add bias (+res) in channel-major order (coalesced res/gmem)
    bool transposed = (OUTMODE == 1) && (bz < 256);
    for (int i = tid; i < 64*128; i += 256) {
        int cl = i >> 7, tl = i & 127;
        int co = sec*64 + cl;
        float v = stage[cl*133 + tl] + __ldg(bias + co);
        if (RES) v += __ldg(res + ((size_t)bz*COUT + co)*TDIM + t0 + tl);
        if (!transposed) {
            outc[((size_t)bz*COUT + co)*TDIM + t0 + tl] = v;
        } else {
            stage[cl*133 + tl] = v;
        }
    }
    if (transposed) {
        __syncthreads();
        int slice = (int)(bz >> 7), b = (int)(bz & 127);
        float* dst = outt + (((size_t)slice*BT) + (size_t)b*TDIM + t0)*DOUT + sec*64;
        for (int i = tid; i < 128*64; i += 256) {
            int tl = i >> 6, cl = i & 63;
            dst[(size_t)tl*DOUT + cl] = stage[cl*133 + tl];
        }
    }
}

// ---- reduce 20 dense partials + b2 -> interp ----
__global__ void reduce_kernel(const float* __restrict__ part,
                              const float* __restrict__ b2,
                              float* __restrict__ interp) {
    int i = blockIdx.x * 256 + threadIdx.x;
    if (i >= BT * DIN) return;
    float s = b2[i % 12];
#pragma unroll
    for (int sec = 0; sec < 20; sec++) s += part[(size_t)sec*BT*DIN + i];
    interp[i] = s;
}

// ---- finale: outputs + masks + passthrough (GRU provably dead: mask1==1) ---
__global__ void finale_kernel(const float* __restrict__ interp,
                              const float* __restrict__ M12, const float* __restrict__ c12,
                              const float* __restrict__ x1, const float* __restrict__ x2,
                              float* __restrict__ o1, float* __restrict__ o2,
                              float* __restrict__ om1, float* __restrict__ om2,
                              float* __restrict__ ox1, float* __restrict__ ox2) {
    int r = blockIdx.x * blockDim.x + threadIdx.x;
    if (r >= BT) return;
    float xv[12];
#pragma unroll
    for (int i = 0; i < 12; i++) xv[i] = interp[r * 12 + i];
#pragma unroll
    for (int j = 0; j < 12; j++) {
        float s = c12[j];
#pragma unroll
        for (int i = 0; i < 12; i++) s += xv[i] * M12[i * 12 + j];
        o1[r * 12 + j] = s;
        o2[r * 12 + j] = s;
    }
#pragma unroll
    for (int j = 0; j < 12; j++) {
        float a = x1[r * 12 + j], b = x2[r * 12 + j];
        om1[r * 12 + j] = (a != 0.f) ? 1.f : 0.f;
        om2[r * 12 + j] = (b != 0.f) ? 1.f : 0.f;
        ox1[r * 12 + j] = a;
        ox2[r * 12 + j] = b;
    }
}

// ---------------- host ----------------
#define SMEM_MMA 74880

extern "C" void kernel_launch(void* const* d_in, const int* in_sizes, int n_in,
                              void* d_out, int out_size) {
    const float* x1 = (const float*)d_in[0];
    const float* x2 = (const float*)d_in[1];
    const float* X1 = (const float*)d_in[2];
    const float* X2 = (const float*)d_in[3];
    const float* w_in = (const float*)d_in[5];
    const float* b_in = (const float*)d_in[6];
    const float* c0_1_w = (const float*)d_in[7];
    const float* c0_1_b = (const float*)d_in[8];
    const float* c0_2_w = (const float*)d_in[9];
    const float* c0_2_b = (const float*)d_in[10];
    const float* c1_p_w = (const float*)d_in[11];
    const float* c1_p_b = (const float*)d_in[12];
    const float* c1_1_w = (const float*)d_in[13];
    const float* c1_1_b = (const float*)d_in[14];
    const float* c1_2_w = (const float*)d_in[15];
    const float* c1_2_b = (const float*)d_in[16];
    const float* ih_dense_w = (const float*)d_in[17];
    const float* ih_dense_b = (const float*)d_in[18];
    const float* ih_proj_w = (const float*)d_in[19];
    const float* ih_proj_b = (const float*)d_in[20];
    const float* fc_w = (const float*)d_in[21];
    const float* fc_b = (const float*)d_in[22];
    const float* fcr_w = (const float*)d_in[29];
    const float* fcr_b = (const float*)d_in[30];

    float *b64a, *b64b, *b64c, *b320a, *b320b, *b320c, *interp, *part, *M12, *c12;
    __nv_bfloat16 *A64h, *A64l, *A320h, *A320l, *img;
    cudaGetSymbolAddress((void**)&b64a, g_b64_a);
    cudaGetSymbolAddress((void**)&b64b, g_b64_b);
    cudaGetSymbolAddress((void**)&b64c, g_b64_c);
    cudaGetSymbolAddress((void**)&b320a, g_b320_a);
    cudaGetSymbolAddress((void**)&b320b, g_b320_b);
    cudaGetSymbolAddress((void**)&b320c, g_b320_c);
    cudaGetSymbolAddress((void**)&interp, g_interp);
    cudaGetSymbolAddress((void**)&part, g_part);
    cudaGetSymbolAddress((void**)&M12, g_M12);
    cudaGetSymbolAddress((void**)&c12, g_c12);
    cudaGetSymbolAddress((void**)&A64h, g_A64h);
    cudaGetSymbolAddress((void**)&A64l, g_A64l);
    cudaGetSymbolAddress((void**)&A320h, g_A320h);
    cudaGetSymbolAddress((void**)&A320l, g_A320l);
    cudaGetSymbolAddress((void**)&img, g_img);

    cudaFuncSetAttribute(conv_mma_kernel<64,64,3,1,false,0>,
                         cudaFuncAttributeMaxDynamicSharedMemorySize, SMEM_MMA);
    cudaFuncSetAttribute(conv_mma_kernel<64,64,3,1,true,0>,
                         cudaFuncAttributeMaxDynamicSharedMemorySize, SMEM_MMA);
    cudaFuncSetAttribute(conv_mma_kernel<64,320,1,1,false,0>,
                         cudaFuncAttributeMaxDynamicSharedMemorySize, SMEM_MMA);
    cudaFuncSetAttribute(conv_mma_kernel<64,320,3,2,false,0>,
                         cudaFuncAttributeMaxDynamicSharedMemorySize, SMEM_MMA);
    cudaFuncSetAttribute(conv_mma_kernel<320,320,3,2,true,1>,
                         cudaFuncAttributeMaxDynamicSharedMemorySize, SMEM_MMA);
    cudaFuncSetAttribute(conv_mma_kernel<320,1280,1,1,false,2>,
                         cudaFuncAttributeMaxDynamicSharedMemorySize, SMEM_MMA);

    float* out = (float*)d_out;
    float* o_o1  = out + 2 * (size_t)BT * DOUT;
    float* o_o2  = o_o1 + (size_t)BT * DIN;
    float* o_m1  = o_o2 + (size_t)BT * DIN;
    float* o_m2  = o_m1 + (size_t)BT * DIN;
    float* o_x1  = o_m2 + (size_t)BT * DIN;
    float* o_x2  = o_x1 + (size_t)BT * DIN;

    setup_kernel<<<3216, 256>>>(c0_1_w, c0_2_w, c1_p_w, c1_1_w, c1_2_w, ih_dense_w,
                                fc_w, fc_b, fcr_w, fcr_b, M12, c12);
    proj_in3_kernel<<<dim3(TDIM / 128, NB), 128>>>(X1, X2, x1, w_in, b_in, b64a);

    dim3 cg64(17, 1, NB), cg320(17, 5, NB), cg320d(17, 5, BB);
    // block0
    cvt_kernel<true><<<cg64, 256>>>(b64a, A64h, A64l);
    conv_mma_kernel<64,64,3,1,false,0><<<dim3(4,1,NB), 256, SMEM_MMA>>>(
        A64h, A64l, img, c0_1_b, nullptr, b64b, nullptr, nullptr, nullptr);
    cvt_kernel<true><<<cg64, 256>>>(b64b, A64h, A64l);
    conv_mma_kernel<64,64,3,1,true,0><<<dim3(4,1,NB), 256, SMEM_MMA>>>(
        A64h, A64l, img + (size_t)3*9216, c0_2_b, b64a, b64c, nullptr, nullptr, nullptr);
    // block1
    cvt_kernel<false><<<cg64, 256>>>(b64c, A64h, A64l);
    conv_mma_kernel<64,320,1,1,false,0><<<dim3(4,5,NB), 256, SMEM_MMA>>>(
        A64h, A64l, img + (size_t)6*9216, c1_p_b, nullptr, b320a, nullptr, nullptr, nullptr);
    cvt_kernel<true><<<cg64, 256>>>(b64c, A64h, A64l);
    conv_mma_kernel<64,320,3,2,false,0><<<dim3(4,5,NB), 256, SMEM_MMA>>>(
        A64h, A64l, img + (size_t)11*9216, c1_1_b, nullptr, b320b, nullptr, nullptr, nullptr);
    cvt_kernel<true><<<cg320, 256>>>(b320b, A320h, A320l);
    conv_mma_kernel<320,320,3,2,true,1><<<dim3(4,5,NB), 256, SMEM_MMA>>>(
        A320h, A320l, img + (size_t)26*9216, c1_2_b, b320a, b320c, out, nullptr, nullptr);
    // dense head on slice 2 (dense2 fused into epilogue -> partials)
    cvt_kernel<false><<<cg320d, 256>>>(b320c + 2*SLICE_OFF, A320h, A320l);
    conv_mma_kernel<320,1280,1,1,false,2><<<dim3(4,20,BB), 256, SMEM_MMA>>>(
        A320h, A320l, img + (size_t)101*9216, ih_dense_b, nullptr,
        nullptr, nullptr, ih_proj_w, part);
    reduce_kernel<<<(BT*DIN + 255)/256, 256>>>(part, ih_proj_b, interp);
    finale_kernel<<<(BT + 127) / 128, 128>>>(interp, M12, c12, x1, x2,
                                             o_o1, o_o2, o_m1, o_m2, o_x1, o_x2);
}

// round 12
// speedup vs baseline: 1.7829x; 1.0214x over previous
#include <cuda_runtime.h>
#include <cuda_bf16.h>
#include <math.h>
#include <stdint.h>

#define BB 128
#define NB 384
#define TDIM 512
#define DIN 12
#define HH 64
#define DOUT 320
#define BT (BB*TDIM)
#define SLICE_OFF ((size_t)BB*DOUT*TDIM)

// ---------------- static scratch ----------------
__device__ float g_b64_a[(size_t)NB*HH*TDIM];
__device__ float g_b64_b[(size_t)NB*HH*TDIM];
__device__ float g_b64_c[(size_t)NB*HH*TDIM];
__device__ float g_b320_a[(size_t)NB*DOUT*TDIM];
__device__ float g_b320_b[(size_t)NB*DOUT*TDIM];
__device__ float g_b320_c[(size_t)NB*DOUT*TDIM];
__device__ float g_interp[BT*DIN];
__device__ float g_part[(size_t)20*BT*DIN];
__device__ float g_M12[144];
__device__ float g_c12[12];
// converted activations: [bz][ch][544 rows (16 pad | 512 | 16 pad)][64 ci] bf16
__device__ __align__(16) __nv_bfloat16 g_A64h[(size_t)NB*544*64];
__device__ __align__(16) __nv_bfloat16 g_A64l[(size_t)NB*544*64];
__device__ __align__(16) __nv_bfloat16 g_A320h[(size_t)NB*5*544*64];
__device__ __align__(16) __nv_bfloat16 g_A320l[(size_t)NB*5*544*64];
// weight images: 201 blocks of [hl 2][n 64][k 72] bf16 (9216 elems each)
__device__ __align__(16) __nv_bfloat16 g_img[(size_t)201*9216];

// ---------------- helpers ----------------
__device__ __forceinline__ uint32_t s2u(const void* p) {
    uint32_t a;
    asm("{ .reg .u64 t; cvta.to.shared.u64 t, %1; cvt.u32.u64 %0, t; }" : "=r"(a) : "l"(p));
    return a;
}
__device__ __forceinline__ void cp16(uint32_t d, const void* s) {
    asm volatile("cp.async.cg.shared.global [%0], [%1], 16;" :: "r"(d), "l"(s));
}
#define CP_COMMIT() asm volatile("cp.async.commit_group;" ::: "memory")
#define CP_WAIT1()  asm volatile("cp.async.wait_group 1;" ::: "memory")
#define CP_WAIT0()  asm volatile("cp.async.wait_group 0;" ::: "memory")

__device__ __forceinline__ void mma16816(float* c, const uint32_t* a, const uint32_t* b) {
    asm volatile(
        "mma.sync.aligned.m16n8k16.row.col.f32.bf16.bf16.f32 "
        "{%0,%1,%2,%3}, {%4,%5,%6,%7}, {%8,%9}, {%0,%1,%2,%3};"
        : "+f"(c[0]), "+f"(c[1]), "+f"(c[2]), "+f"(c[3])
        : "r"(a[0]), "r"(a[1]), "r"(a[2]), "r"(a[3]), "r"(b[0]), "r"(b[1]));
}
__device__ __forceinline__ float gelu1(float x) {
    return 0.5f * x * (1.0f + erff(x * 0.7071067811865476f));
}

// ---------------- setup: weight images (hi/lo bf16) + M12 ----------------
__global__ void setup_kernel(
    const float* __restrict__ c01w, const float* __restrict__ c02w,
    const float* __restrict__ c1pw, const float* __restrict__ c11w,
    const float* __restrict__ c12w, const float* __restrict__ dw,
    const float* __restrict__ fc_w, const float* __restrict__ fc_b,
    const float* __restrict__ fcr_w, const float* __restrict__ fcr_b,
    float* __restrict__ M12, float* __restrict__ c12)
{
    const int TOT = 201 * 4096;
    int stride = gridDim.x * 256;
    for (int i = blockIdx.x*256 + threadIdx.x; i < TOT; i += stride) {
        int blk = i >> 12, e = i & 4095;
        int n = e >> 6, k = e & 63;
        float w;
        if (blk < 3) {
            w = c01w[(n*64 + k)*3 + blk];
        } else if (blk < 6) {
            w = c02w[(n*64 + k)*3 + (blk - 3)];
        } else if (blk < 11) {
            int s = blk - 6;
            w = c1pw[(s*64 + n)*64 + k];
        } else if (blk < 26) {
            int r = blk - 11, s = r/3, tap = r%3;
            w = c11w[((s*64 + n)*64 + k)*3 + tap];
        } else if (blk < 101) {
            int r = blk - 26, s = r/15, r2 = r%15, ch = r2/3, tap = r2%3;
            w = c12w[((s*64 + n)*320 + ch*64 + k)*3 + tap];
        } else {
            int r = blk - 101, s = r/5, ch = r%5;
            w = dw[(ch*64 + k)*1280 + s*64 + n];
        }
        size_t base = (size_t)blk * 9216;
        uint32_t idx = (uint32_t)n * 72 + (uint32_t)k;
        __nv_bfloat16 h = __float2bfloat16(w);
        g_img[base + idx] = h;
        g_img[base + 4608 + idx] = __float2bfloat16(w - __bfloat162float(h));
    }
    if (blockIdx.x == 0) {
        int tid = threadIdx.x;
        if (tid < 144) {
            int a = tid / 12, bj = tid % 12;
            float s = 0.f;
            for (int k = 0; k < DOUT; k++) s += fc_w[a*DOUT + k] * fcr_w[k*12 + bj];
            M12[tid] = s;
        } else if (tid < 156) {
            int bj = tid - 144;
            float s = fcr_b[bj];
            for (int k = 0; k < DOUT; k++) s += fc_b[k] * fcr_w[k*12 + bj];
            c12[bj] = s;
        }
    }
}

// ---------------- input projection, all 3 slices ----------------
__global__ void proj_in3_kernel(const float* __restrict__ X1, const float* __restrict__ X2,
                                const float* __restrict__ x1,
                                const float* __restrict__ w, const float* __restrict__ bi,
                                float* __restrict__ out) {
    int bz = blockIdx.y;
    int slice = bz >> 7, b = bz & 127;
    const float* x = (slice == 0) ? X1 : (slice == 1) ? X2 : x1;
    int t = blockIdx.x * 128 + threadIdx.x;
    float xv[DIN];
#pragma unroll
    for (int i = 0; i < DIN; i++) xv[i] = x[(b * TDIM + t) * DIN + i];
    for (int c = 0; c < HH; c++) {
        float s = bi[c];
#pragma unroll
        for (int i = 0; i < DIN; i++) s += xv[i] * w[i * HH + c];
        out[((size_t)bz * HH + c) * TDIM + t] = s;
    }
}

// ------- convert f32 [bz][CH*64][512] -> bf16 hi/lo [bz][ch][544][64] --------
template<bool GELU>
__global__ __launch_bounds__(256) void cvt_kernel(
    const float* __restrict__ in,
    __nv_bfloat16* __restrict__ oh, __nv_bfloat16* __restrict__ ol)
{
    __shared__ float s[64][33];
    int j0 = blockIdx.x * 32;
    int ch = blockIdx.y, CH = gridDim.y;
    size_t bz = blockIdx.z;
    int tid = threadIdx.x;
    const float* src = in + ((size_t)bz * CH + ch) * 64 * TDIM;
    for (int i = tid; i < 64*32; i += 256) {
        int ci = i >> 5, jj = i & 31;
        int t = j0 + jj - 16;
        float v = 0.f;
        if (t >= 0 && t < TDIM) {
            v = src[(size_t)ci*TDIM + t];
            if (GELU) v = gelu1(v);
        }
        s[ci][jj] = v;
    }
    __syncthreads();
    size_t ob = (((size_t)bz * CH + ch) * 544 + j0) * 64;
    for (int i = tid; i < 64*32; i += 256) {
        int jj = i >> 6, ci = i & 63;
        float v = s[ci][jj];
        __nv_bfloat16 h = __float2bfloat16(v);
        oh[ob + (size_t)jj*64 + ci] = h;
        ol[ob + (size_t)jj*64 + ci] = __float2bfloat16(v - __bfloat162float(h));
    }
}

// ---------------- tensor-core conv via mma.sync (split bf16, 3-pass) --------
// CTA tile M=256 x N=64; 8 warps (4M x 2N), warp tile 64x32 -> 128 B/MMA.
// Single A buffer (260 rows hi/lo) + double B -> 111744 B smem, 2 CTAs/SM.
// OUTMODE: 0 = channel-major f32; 1 = conv12 (slices 0/1 transposed to d_out,
//          slice 2 channel-major); 2 = dense head (relu + W2 partial to g_part)
template<int CIN, int COUT, int TAPS, int DIL, bool RES, int OUTMODE>
__global__ __launch_bounds__(256, 2) void conv_mma_kernel(
    const __nv_bfloat16* __restrict__ gAh, const __nv_bfloat16* __restrict__ gAl,
    const __nv_bfloat16* __restrict__ img,
    const float* __restrict__ bias, const float* __restrict__ res,
    float* __restrict__ outc, float* __restrict__ outt,
    const float* __restrict__ W2, float* __restrict__ part)
{
    constexpr int CHUNKS = CIN / 64;
    constexpr int NITER = CHUNKS * TAPS;
    extern __shared__ __align__(16) char smem[];
    uint32_t sb = s2u(smem);

    int tid = threadIdx.x, lane = tid & 31, wid = tid >> 5;
    int g = lane >> 2, q = lane & 3;
    int wm = wid >> 1, wn = wid & 1;
    size_t bz = blockIdx.z;
    int t0 = blockIdx.x * 256, sec = blockIdx.y;

    float acc[4][4][4];
#pragma unroll
    for (int a = 0; a < 4; a++)
#pragma unroll
        for (int b = 0; b < 4; b++)
#pragma unroll
            for (int c = 0; c < 4; c++) acc[a][b][c] = 0.f;

    // A: [0, 74880) single buffer (hi 37440 | lo 37440), 260 rows x 72 stride
    // B: [74880, 111744) two buffers of 18432
    auto loadA = [&](int ch) {
        size_t rowbase = ((size_t)bz * CHUNKS + ch) * 544 + (16 + t0 - 2);
        for (int i = tid; i < 4160; i += 256) {
            int hl = (i >= 2080) ? 1 : 0;
            int rr = i - hl * 2080;
            int r = rr >> 3, c = rr & 7;
            const __nv_bfloat16* gsrc = (hl ? gAl : gAh) + (rowbase + r) * 64 + c * 8;
            cp16(sb + hl*37440 + r*144 + c*16, gsrc);
        }
    };
    auto loadB = [&](int it2, int slot) {
        const char* gsrc = (const char*)(img + ((size_t)sec * NITER + it2) * 9216);
        for (int i = tid; i < 1152; i += 256)
            cp16(sb + 74880 + slot*18432 + i*16, gsrc + i*16);
    };

    loadB(0, 0);
    CP_COMMIT();

    int it = 0;
    for (int ch = 0; ch < CHUNKS; ch++) {
        for (int tap = 0; tap < TAPS; tap++, it++) {
            __syncthreads();     // prior compute done: A buffer / B slot safe
            if (tap == 0) { loadA(ch); CP_COMMIT(); }
            if (it + 1 < NITER) {
                loadB(it + 1, (it + 1) & 1);
                CP_COMMIT();
                CP_WAIT1();      // A (if any) + B(it) complete; B(it+1) in flight
            } else {
                CP_WAIT0();
            }
            __syncthreads();
            const __nv_bfloat16* sAh = (const __nv_bfloat16*)smem;
            const __nv_bfloat16* sAl = sAh + 18720;
            const __nv_bfloat16* sBh = (const __nv_bfloat16*)(smem + 74880 + (it & 1)*18432);
            const __nv_bfloat16* sBl = sBh + 4608;
            int rb = 2 + (tap - TAPS/2)*DIL + wm*64 + g;
#pragma unroll
            for (int ks = 0; ks < 4; ks++) {
                int kc = ks*16 + q*2;
                uint32_t ah[4][4], al[4][4], bh[4][2], bl[4][2];
#pragma unroll
                for (int mt = 0; mt < 4; mt++) {
                    int base = (rb + mt*16)*72 + kc;
                    ah[mt][0] = *(const uint32_t*)(sAh + base);
                    ah[mt][1] = *(const uint32_t*)(sAh + base + 8*72);
                    ah[mt][2] = *(const uint32_t*)(sAh + base + 8);
                    ah[mt][3] = *(const uint32_t*)(sAh + base + 8*72 + 8);
                    al[mt][0] = *(const uint32_t*)(sAl + base);
                    al[mt][1] = *(const uint32_t*)(sAl + base + 8*72);
                    al[mt][2] = *(const uint32_t*)(sAl + base + 8);
                    al[mt][3] = *(const uint32_t*)(sAl + base + 8*72 + 8);
                }
#pragma unroll
                for (int nt = 0; nt < 4; nt++) {
                    int nb = (wn*32 + nt*8 + g)*72 + kc;
                    bh[nt][0] = *(const uint32_t*)(sBh + nb);
                    bh[nt][1] = *(const uint32_t*)(sBh + nb + 8);
                    bl[nt][0] = *(const uint32_t*)(sBl + nb);
                    bl[nt][1] = *(const uint32_t*)(sBl + nb + 8);
                }
#pragma unroll
                for (int mt = 0; mt < 4; mt++)
#pragma unroll
                    for (int nt = 0; nt < 4; nt++) {
                        mma16816(acc[mt][nt], ah[mt], bh[nt]);
                        mma16816(acc[mt][nt], al[mt], bh[nt]);
                        mma16816(acc[mt][nt], ah[mt], bl[nt]);
                    }
            }
        }
    }
    // -------- epilogue --------
    __syncthreads();
    float* stage = (float*)smem;          // [n 64][m 256] at stride 261 (odd)
#pragma unroll
    for (int mt = 0; mt < 4; mt++)
#pragma unroll
        for (int nt = 0; nt < 4; nt++) {
            int m = wm*64 + mt*16 + g;
            int n = wn*32 + nt*8 + q*2;
            stage[n*261 + m]         = acc[mt][nt][0];
            stage[(n+1)*261 + m]     = acc[mt][nt][1];
            stage[n*261 + m + 8]     = acc[mt][nt][2];
            stage[(n+1)*261 + m + 8] = acc[mt][nt][3];
        }
    __syncthreads();

    if (OUTMODE == 2) {
        float* sW2 = (float*)(smem + 67072);   // 64*12 f32
        float* sB1 = sW2 + 64*12;              // 64 f32
        for (int i = tid; i < 64*12; i += 256)
            sW2[i] = __ldg(W2 + (sec*64 + i/12)*12 + (i%12));
        if (tid < 64) sB1[tid] = __ldg(bias + sec*64 + tid);
        __syncthreads();
        for (int i = tid; i < 256*12; i += 256) {
            int tl = i / 12, o = i % 12;
            float s = 0.f;
#pragma unroll 8
            for (int cl = 0; cl < 64; cl++) {
                float v = stage[cl*261 + tl] + sB1[cl];
                v = v > 0.f ? v : 0.f;
                s += v * sW2[cl*12 + o];
            }
            part[((size_t)sec*BT + bz*TDIM + t0 + tl)*12 + o] = s;
        }
        return;
    }

    // add bias (+res) in channel-major order (coalesced res/gmem)
    bool transposed = (OUTMODE == 1) && (bz < 256);
    for (int i = tid; i < 64*256; i += 256) {
        int cl = i >> 8, tl = i & 255;
        int co = sec*64 + cl;
        float v = stage[cl*261 + tl] + __ldg(bias + co);
        if (RES) v += __ldg(res + ((size_t)bz*COUT + co)*TDIM + t0 + tl);
        if (!transposed) {
            outc[((size_t)bz*COUT + co)*TDIM + t0 + tl] = v;
        } else {
            stage[cl*261 + tl] = v;
        }
    }
    if (transposed) {
        __syncthreads();
        int slice = (int)(bz >> 7), b = (int)(bz & 127);
        float* dst = outt + (((size_t)slice*BT) + (size_t)b*TDIM + t0)*DOUT + sec*64;
        for (int i = tid; i < 256*64; i += 256) {
            int tl = i >> 6, cl = i & 63;
            dst[(size_t)tl*DOUT + cl] = stage[cl*261 + tl];
        }
    }
}

// ---- reduce 20 dense partials + b2 -> interp ----
__global__ void reduce_kernel(const float* __restrict__ part,
                              const float* __restrict__ b2,
                              float* __restrict__ interp) {
    int i = blockIdx.x * 256 + threadIdx.x;
    if (i >= BT * DIN) return;
    float s = b2[i % 12];
#pragma unroll
    for (int sec = 0; sec < 20; sec++) s += part[(size_t)sec*BT*DIN + i];
    interp[i] = s;
}

// ---- finale: outputs + masks + passthrough (GRU provably dead: mask1==1) ---
__global__ void finale_kernel(const float* __restrict__ interp,
                              const float* __restrict__ M12, const float* __restrict__ c12,
                              const float* __restrict__ x1, const float* __restrict__ x2,
                              float* __restrict__ o1, float* __restrict__ o2,
                              float* __restrict__ om1, float* __restrict__ om2,
                              float* __restrict__ ox1, float* __restrict__ ox2) {
    int r = blockIdx.x * blockDim.x + threadIdx.x;
    if (r >= BT) return;
    float xv[12];
#pragma unroll
    for (int i = 0; i < 12; i++) xv[i] = interp[r * 12 + i];
#pragma unroll
    for (int j = 0; j < 12; j++) {
        float s = c12[j];
#pragma unroll
        for (int i = 0; i < 12; i++) s += xv[i] * M12[i * 12 + j];
        o1[r * 12 + j] = s;
        o2[r * 12 + j] = s;
    }
#pragma unroll
    for (int j = 0; j < 12; j++) {
        float a = x1[r * 12 + j], b = x2[r * 12 + j];
        om1[r * 12 + j] = (a != 0.f) ? 1.f : 0.f;
        om2[r * 12 + j] = (b != 0.f) ? 1.f : 0.f;
        ox1[r * 12 + j] = a;
        ox2[r * 12 + j] = b;
    }
}

// ---------------- host ----------------
#define SMEM_MMA 111744

extern "C" void kernel_launch(void* const* d_in, const int* in_sizes, int n_in,
                              void* d_out, int out_size) {
    const float* x1 = (const float*)d_in[0];
    const float* x2 = (const float*)d_in[1];
    const float* X1 = (const float*)d_in[2];
    const float* X2 = (const float*)d_in[3];
    const float* w_in = (const float*)d_in[5];
    const float* b_in = (const float*)d_in[6];
    const float* c0_1_w = (const float*)d_in[7];
    const float* c0_1_b = (const float*)d_in[8];
    const float* c0_2_w = (const float*)d_in[9];
    const float* c0_2_b = (const float*)d_in[10];
    const float* c1_p_w = (const float*)d_in[11];
    const float* c1_p_b = (const float*)d_in[12];
    const float* c1_1_w = (const float*)d_in[13];
    const float* c1_1_b = (const float*)d_in[14];
    const float* c1_2_w = (const float*)d_in[15];
    const float* c1_2_b = (const float*)d_in[16];
    const float* ih_dense_w = (const float*)d_in[17];
    const float* ih_dense_b = (const float*)d_in[18];
    const float* ih_proj_w = (const float*)d_in[19];
    const float* ih_proj_b = (const float*)d_in[20];
    const float* fc_w = (const float*)d_in[21];
    const float* fc_b = (const float*)d_in[22];
    const float* fcr_w = (const float*)d_in[29];
    const float* fcr_b = (const float*)d_in[30];

    float *b64a, *b64b, *b64c, *b320a, *b320b, *b320c, *interp, *part, *M12, *c12;
    __nv_bfloat16 *A64h, *A64l, *A320h, *A320l, *img;
    cudaGetSymbolAddress((void**)&b64a, g_b64_a);
    cudaGetSymbolAddress((void**)&b64b, g_b64_b);
    cudaGetSymbolAddress((void**)&b64c, g_b64_c);
    cudaGetSymbolAddress((void**)&b320a, g_b320_a);
    cudaGetSymbolAddress((void**)&b320b, g_b320_b);
    cudaGetSymbolAddress((void**)&b320c, g_b320_c);
    cudaGetSymbolAddress((void**)&interp, g_interp);
    cudaGetSymbolAddress((void**)&part, g_part);
    cudaGetSymbolAddress((void**)&M12, g_M12);
    cudaGetSymbolAddress((void**)&c12, g_c12);
    cudaGetSymbolAddress((void**)&A64h, g_A64h);
    cudaGetSymbolAddress((void**)&A64l, g_A64l);
    cudaGetSymbolAddress((void**)&A320h, g_A320h);
    cudaGetSymbolAddress((void**)&A320l, g_A320l);
    cudaGetSymbolAddress((void**)&img, g_img);

    cudaFuncSetAttribute(conv_mma_kernel<64,64,3,1,false,0>,
                         cudaFuncAttributeMaxDynamicSharedMemorySize, SMEM_MMA);
    cudaFuncSetAttribute(conv_mma_kernel<64,64,3,1,true,0>,
                         cudaFuncAttributeMaxDynamicSharedMemorySize, SMEM_MMA);
    cudaFuncSetAttribute(conv_mma_kernel<64,320,1,1,false,0>,
                         cudaFuncAttributeMaxDynamicSharedMemorySize, SMEM_MMA);
    cudaFuncSetAttribute(conv_mma_kernel<64,320,3,2,false,0>,
                         cudaFuncAttributeMaxDynamicSharedMemorySize, SMEM_MMA);
    cudaFuncSetAttribute(conv_mma_kernel<320,320,3,2,true,1>,
                         cudaFuncAttributeMaxDynamicSharedMemorySize, SMEM_MMA);
    cudaFuncSetAttribute(conv_mma_kernel<320,1280,1,1,false,2>,
                         cudaFuncAttributeMaxDynamicSharedMemorySize, SMEM_MMA);

    float* out = (float*)d_out;
    float* o_o1  = out + 2 * (size_t)BT * DOUT;
    float* o_o2  = o_o1 + (size_t)BT * DIN;
    float* o_m1  = o_o2 + (size_t)BT * DIN;
    float* o_m2  = o_m1 + (size_t)BT * DIN;
    float* o_x1  = o_m2 + (size_t)BT * DIN;
    float* o_x2  = o_x1 + (size_t)BT * DIN;

    setup_kernel<<<3216, 256>>>(c0_1_w, c0_2_w, c1_p_w, c1_1_w, c1_2_w, ih_dense_w,
                                fc_w, fc_b, fcr_w, fcr_b, M12, c12);
    proj_in3_kernel<<<dim3(TDIM / 128, NB), 128>>>(X1, X2, x1, w_in, b_in, b64a);

    dim3 cg64(17, 1, NB), cg320(17, 5, NB), cg320d(17, 5, BB);
    // block0
    cvt_kernel<true><<<cg64, 256>>>(b64a, A64h, A64l);
    conv_mma_kernel<64,64,3,1,false,0><<<dim3(2,1,NB), 256, SMEM_MMA>>>(
        A64h, A64l, img, c0_1_b, nullptr, b64b, nullptr, nullptr, nullptr);
    cvt_kernel<true><<<cg64, 256>>>(b64b, A64h, A64l);
    conv_mma_kernel<64,64,3,1,true,0><<<dim3(2,1,NB), 256, SMEM_MMA>>>(
        A64h, A64l, img + (size_t)3*9216, c0_2_b, b64a, b64c, nullptr, nullptr, nullptr);
    // block1
    cvt_kernel<false><<<cg64, 256>>>(b64c, A64h, A64l);
    conv_mma_kernel<64,320,1,1,false,0><<<dim3(2,5,NB), 256, SMEM_MMA>>>(
        A64h, A64l, img + (size_t)6*9216, c1_p_b, nullptr, b320a, nullptr, nullptr, nullptr);
    cvt_kernel<true><<<cg64, 256>>>(b64c, A64h, A64l);
    conv_mma_kernel<64,320,3,2,false,0><<<dim3(2,5,NB), 256, SMEM_MMA>>>(
        A64h, A64l, img + (size_t)11*9216, c1_1_b, nullptr, b320b, nullptr, nullptr, nullptr);
    cvt_kernel<true><<<cg320, 256>>>(b320b, A320h, A320l);
    conv_mma_kernel<320,320,3,2,true,1><<<dim3(2,5,NB), 256, SMEM_MMA>>>(
        A320h, A320l, img + (size_t)26*9216, c1_2_b, b320a, b320c, out, nullptr, nullptr);
    // dense head on slice 2 (dense2 fused into epilogue -> partials)
    cvt_kernel<false><<<cg320d, 256>>>(b320c + 2*SLICE_OFF, A320h, A320l);
    conv_mma_kernel<320,1280,1,1,false,2><<<dim3(2,20,BB), 256, SMEM_MMA>>>(
        A320h, A320l, img + (size_t)101*9216, ih_dense_b, nullptr,
        nullptr, nullptr, ih_proj_w, part);
    reduce_kernel<<<(BT*DIN + 255)/256, 256>>>(part, ih_proj_b, interp);
    finale_kernel<<<(BT + 127) / 128, 128>>>(interp, M12, c12, x1, x2,
                                             o_o1, o_o2, o_m1, o_m2, o_x1, o_x2);
}

// round 13
// speedup vs baseline: 1.8365x; 1.0301x over previous
#include <cuda_runtime.h>
#include <cuda_bf16.h>
#include <math.h>
#include <stdint.h>

#define BB 128
#define NB 384
#define TDIM 512
#define DIN 12
#define HH 64
#define DOUT 320
#define BT (BB*TDIM)

// ---------------- static scratch ----------------
__device__ float g_b64_a[(size_t)NB*HH*TDIM];     // proj f32 (residual for conv02)
__device__ float g_b320_a[(size_t)NB*DOUT*TDIM];  // c1p f32 (residual for conv12)
__device__ float g_interp[BT*DIN];
__device__ float g_part[(size_t)20*BT*DIN];
__device__ float g_M12[144];
__device__ float g_c12[12];
// A-format activations: [bz][ch][544 rows (16 pad | 512 | 16 pad)][64 ci] bf16
// pads never written -> stay zero from static init
__device__ __align__(16) __nv_bfloat16 g_Aga_h[(size_t)NB*544*64];  // gelu buf A
__device__ __align__(16) __nv_bfloat16 g_Aga_l[(size_t)NB*544*64];
__device__ __align__(16) __nv_bfloat16 g_Agb_h[(size_t)NB*544*64];  // gelu buf B
__device__ __align__(16) __nv_bfloat16 g_Agb_l[(size_t)NB*544*64];
__device__ __align__(16) __nv_bfloat16 g_Ang_h[(size_t)NB*544*64];  // non-gelu
__device__ __align__(16) __nv_bfloat16 g_Ang_l[(size_t)NB*544*64];
__device__ __align__(16) __nv_bfloat16 g_A320h[(size_t)NB*5*544*64];
__device__ __align__(16) __nv_bfloat16 g_A320l[(size_t)NB*5*544*64];
__device__ __align__(16) __nv_bfloat16 g_A320h2[(size_t)BB*5*544*64];
__device__ __align__(16) __nv_bfloat16 g_A320l2[(size_t)BB*5*544*64];
// weight images: 201 blocks of [hl 2][n 64][k 72] bf16 (9216 elems each)
__device__ __align__(16) __nv_bfloat16 g_img[(size_t)201*9216];

// ---------------- helpers ----------------
__device__ __forceinline__ uint32_t s2u(const void* p) {
    uint32_t a;
    asm("{ .reg .u64 t; cvta.to.shared.u64 t, %1; cvt.u32.u64 %0, t; }" : "=r"(a) : "l"(p));
    return a;
}
__device__ __forceinline__ void cp16(uint32_t d, const void* s) {
    asm volatile("cp.async.cg.shared.global [%0], [%1], 16;" :: "r"(d), "l"(s));
}
#define CP_COMMIT() asm volatile("cp.async.commit_group;" ::: "memory")
#define CP_WAIT1()  asm volatile("cp.async.wait_group 1;" ::: "memory")
#define CP_WAIT0()  asm volatile("cp.async.wait_group 0;" ::: "memory")

__device__ __forceinline__ void mma16816(float* c, const uint32_t* a, const uint32_t* b) {
    asm volatile(
        "mma.sync.aligned.m16n8k16.row.col.f32.bf16.bf16.f32 "
        "{%0,%1,%2,%3}, {%4,%5,%6,%7}, {%8,%9}, {%0,%1,%2,%3};"
        : "+f"(c[0]), "+f"(c[1]), "+f"(c[2]), "+f"(c[3])
        : "r"(a[0]), "r"(a[1]), "r"(a[2]), "r"(a[3]), "r"(b[0]), "r"(b[1]));
}
__device__ __forceinline__ float gelu1(float x) {
    return 0.5f * x * (1.0f + erff(x * 0.7071067811865476f));
}

// ---------------- setup: weight images (hi/lo bf16) + M12 ----------------
__global__ void setup_kernel(
    const float* __restrict__ c01w, const float* __restrict__ c02w,
    const float* __restrict__ c1pw, const float* __restrict__ c11w,
    const float* __restrict__ c12w, const float* __restrict__ dw,
    const float* __restrict__ fc_w, const float* __restrict__ fc_b,
    const float* __restrict__ fcr_w, const float* __restrict__ fcr_b,
    float* __restrict__ M12, float* __restrict__ c12)
{
    const int TOT = 201 * 4096;
    int stride = gridDim.x * 256;
    for (int i = blockIdx.x*256 + threadIdx.x; i < TOT; i += stride) {
        int blk = i >> 12, e = i & 4095;
        int n = e >> 6, k = e & 63;
        float w;
        if (blk < 3) {
            w = c01w[(n*64 + k)*3 + blk];
        } else if (blk < 6) {
            w = c02w[(n*64 + k)*3 + (blk - 3)];
        } else if (blk < 11) {
            int s = blk - 6;
            w = c1pw[(s*64 + n)*64 + k];
        } else if (blk < 26) {
            int r = blk - 11, s = r/3, tap = r%3;
            w = c11w[((s*64 + n)*64 + k)*3 + tap];
        } else if (blk < 101) {
            int r = blk - 26, s = r/15, r2 = r%15, ch = r2/3, tap = r2%3;
            w = c12w[((s*64 + n)*320 + ch*64 + k)*3 + tap];
        } else {
            int r = blk - 101, s = r/5, ch = r%5;
            w = dw[(ch*64 + k)*1280 + s*64 + n];
        }
        size_t base = (size_t)blk * 9216;
        uint32_t idx = (uint32_t)n * 72 + (uint32_t)k;
        __nv_bfloat16 h = __float2bfloat16(w);
        g_img[base + idx] = h;
        g_img[base + 4608 + idx] = __float2bfloat16(w - __bfloat162float(h));
    }
    if (blockIdx.x == 0) {
        int tid = threadIdx.x;
        if (tid < 144) {
            int a = tid / 12, bj = tid % 12;
            float s = 0.f;
            for (int k = 0; k < DOUT; k++) s += fc_w[a*DOUT + k] * fcr_w[k*12 + bj];
            M12[tid] = s;
        } else if (tid < 156) {
            int bj = tid - 144;
            float s = fcr_b[bj];
            for (int k = 0; k < DOUT; k++) s += fc_b[k] * fcr_w[k*12 + bj];
            c12[bj] = s;
        }
    }
}

// ---------------- input projection, all 3 slices; writes f32 + gelu A --------
__global__ void proj_in3_kernel(const float* __restrict__ X1, const float* __restrict__ X2,
                                const float* __restrict__ x1,
                                const float* __restrict__ w, const float* __restrict__ bi,
                                float* __restrict__ outf,
                                __nv_bfloat16* __restrict__ oAh,
                                __nv_bfloat16* __restrict__ oAl) {
    int bz = blockIdx.y;
    int slice = bz >> 7, b = bz & 127;
    const float* x = (slice == 0) ? X1 : (slice == 1) ? X2 : x1;
    int t = blockIdx.x * 128 + threadIdx.x;
    float xv[DIN];
#pragma unroll
    for (int i = 0; i < DIN; i++) xv[i] = x[(b * TDIM + t) * DIN + i];
    size_t abase = ((size_t)bz * 544 + 16 + t) * 64;
    for (int c = 0; c < HH; c++) {
        float s = bi[c];
#pragma unroll
        for (int i = 0; i < DIN; i++) s += xv[i] * w[i * HH + c];
        outf[((size_t)bz * HH + c) * TDIM + t] = s;
        float gv = gelu1(s);
        __nv_bfloat16 h = __float2bfloat16(gv);
        oAh[abase + c] = h;
        oAl[abase + c] = __float2bfloat16(gv - __bfloat162float(h));
    }
}

// ---------------- tensor-core conv via mma.sync (split bf16, 3-pass) --------
// CTA tile M=256 x N=64; 8 warps (4M x 2N), warp tile 64x32.
// OUTMODE: 0 = f32 channel-major (+bias,+res)
//          1 = conv12: slices 0/1 transposed f32 to d_out; slice 2 raw A h/l
//          2 = dense head (relu + W2 partial to g_part)
//          3 = gelu A h/l (+bias)
//          4 = conv02: raw A h/l (oAh2/l2) AND gelu A h/l (oAh/l), +bias+res
template<int CIN, int COUT, int TAPS, int DIL, bool RES, int OUTMODE>
__global__ __launch_bounds__(256, 2) void conv_mma_kernel(
    const __nv_bfloat16* __restrict__ gAh, const __nv_bfloat16* __restrict__ gAl,
    const __nv_bfloat16* __restrict__ img,
    const float* __restrict__ bias, const float* __restrict__ res,
    float* __restrict__ outc, float* __restrict__ outt,
    const float* __restrict__ W2, float* __restrict__ part,
    __nv_bfloat16* __restrict__ oAh, __nv_bfloat16* __restrict__ oAl,
    __nv_bfloat16* __restrict__ oAh2, __nv_bfloat16* __restrict__ oAl2)
{
    constexpr int CHUNKS = CIN / 64;
    constexpr int CHOUT = COUT / 64;
    constexpr int NITER = CHUNKS * TAPS;
    extern __shared__ __align__(16) char smem[];
    uint32_t sb = s2u(smem);

    int tid = threadIdx.x, lane = tid & 31, wid = tid >> 5;
    int g = lane >> 2, q = lane & 3;
    int wm = wid >> 1, wn = wid & 1;
    size_t bz = blockIdx.z;
    int t0 = blockIdx.x * 256, sec = blockIdx.y;

    float acc[4][4][4];
#pragma unroll
    for (int a = 0; a < 4; a++)
#pragma unroll
        for (int b = 0; b < 4; b++)
#pragma unroll
            for (int c = 0; c < 4; c++) acc[a][b][c] = 0.f;

    // A: [0, 74880) single buffer (hi 37440 | lo 37440), 260 rows x 72 stride
    // B: [74880, 111744) two buffers of 18432
    auto loadA = [&](int ch) {
        size_t rowbase = ((size_t)bz * CHUNKS + ch) * 544 + (16 + t0 - 2);
        for (int i = tid; i < 4160; i += 256) {
            int hl = (i >= 2080) ? 1 : 0;
            int rr = i - hl * 2080;
            int r = rr >> 3, c = rr & 7;
            const __nv_bfloat16* gsrc = (hl ? gAl : gAh) + (rowbase + r) * 64 + c * 8;
            cp16(sb + hl*37440 + r*144 + c*16, gsrc);
        }
    };
    auto loadB = [&](int it2, int slot) {
        const char* gsrc = (const char*)(img + ((size_t)sec * NITER + it2) * 9216);
        for (int i = tid; i < 1152; i += 256)
            cp16(sb + 74880 + slot*18432 + i*16, gsrc + i*16);
    };

    loadB(0, 0);
    CP_COMMIT();

    int it = 0;
    for (int ch = 0; ch < CHUNKS; ch++) {
        for (int tap = 0; tap < TAPS; tap++, it++) {
            __syncthreads();     // prior compute done: A buffer / B slot safe
            if (tap == 0) { loadA(ch); CP_COMMIT(); }
            if (it + 1 < NITER) {
                loadB(it + 1, (it + 1) & 1);
                CP_COMMIT();
                CP_WAIT1();      // A (if any) + B(it) complete; B(it+1) in flight
            } else {
                CP_WAIT0();
            }
            __syncthreads();
            const __nv_bfloat16* sAh = (const __nv_bfloat16*)smem;
            const __nv_bfloat16* sAl = sAh + 18720;
            const __nv_bfloat16* sBh = (const __nv_bfloat16*)(smem + 74880 + (it & 1)*18432);
            const __nv_bfloat16* sBl = sBh + 4608;
            int rb = 2 + (tap - TAPS/2)*DIL + wm*64 + g;
#pragma unroll
            for (int ks = 0; ks < 4; ks++) {
                int kc = ks*16 + q*2;
                uint32_t ah[4][4], al[4][4], bh[4][2], bl[4][2];
#pragma unroll
                for (int mt = 0; mt < 4; mt++) {
                    int base = (rb + mt*16)*72 + kc;
                    ah[mt][0] = *(const uint32_t*)(sAh + base);
                    ah[mt][1] = *(const uint32_t*)(sAh + base + 8*72);
                    ah[mt][2] = *(const uint32_t*)(sAh + base + 8);
                    ah[mt][3] = *(const uint32_t*)(sAh + base + 8*72 + 8);
                    al[mt][0] = *(const uint32_t*)(sAl + base);
                    al[mt][1] = *(const uint32_t*)(sAl + base + 8*72);
                    al[mt][2] = *(const uint32_t*)(sAl + base + 8);
                    al[mt][3] = *(const uint32_t*)(sAl + base + 8*72 + 8);
                }
#pragma unroll
                for (int nt = 0; nt < 4; nt++) {
                    int nb = (wn*32 + nt*8 + g)*72 + kc;
                    bh[nt][0] = *(const uint32_t*)(sBh + nb);
                    bh[nt][1] = *(const uint32_t*)(sBh + nb + 8);
                    bl[nt][0] = *(const uint32_t*)(sBl + nb);
                    bl[nt][1] = *(const uint32_t*)(sBl + nb + 8);
                }
#pragma unroll
                for (int mt = 0; mt < 4; mt++)
#pragma unroll
                    for (int nt = 0; nt < 4; nt++) {
                        mma16816(acc[mt][nt], ah[mt], bh[nt]);
                        mma16816(acc[mt][nt], al[mt], bh[nt]);
                        mma16816(acc[mt][nt], ah[mt], bl[nt]);
                    }
            }
        }
    }
    // -------- epilogue --------
    __syncthreads();
    float* stage = (float*)smem;          // [n 64][m 256] at stride 261 (odd)
#pragma unroll
    for (int mt = 0; mt < 4; mt++)
#pragma unroll
        for (int nt = 0; nt < 4; nt++) {
            int m = wm*64 + mt*16 + g;
            int n = wn*32 + nt*8 + q*2;
            stage[n*261 + m]         = acc[mt][nt][0];
            stage[(n+1)*261 + m]     = acc[mt][nt][1];
            stage[n*261 + m + 8]     = acc[mt][nt][2];
            stage[(n+1)*261 + m + 8] = acc[mt][nt][3];
        }
    __syncthreads();

    if (OUTMODE == 2) {
        float* sW2 = (float*)(smem + 67072);   // 64*12 f32
        float* sB1 = sW2 + 64*12;              // 64 f32
        for (int i = tid; i < 64*12; i += 256)
            sW2[i] = __ldg(W2 + (sec*64 + i/12)*12 + (i%12));
        if (tid < 64) sB1[tid] = __ldg(bias + sec*64 + tid);
        __syncthreads();
        for (int i = tid; i < 256*12; i += 256) {
            int tl = i / 12, o = i % 12;
            float s = 0.f;
#pragma unroll 8
            for (int cl = 0; cl < 64; cl++) {
                float v = stage[cl*261 + tl] + sB1[cl];
                v = v > 0.f ? v : 0.f;
                s += v * sW2[cl*12 + o];
            }
            part[((size_t)sec*BT + bz*TDIM + t0 + tl)*12 + o] = s;
        }
        return;
    }

    if (OUTMODE == 0) {
        for (int i = tid; i < 64*256; i += 256) {
            int cl = i >> 8, tl = i & 255;
            int co = sec*64 + cl;
            float v = stage[cl*261 + tl] + __ldg(bias + co);
            if (RES) v += __ldg(res + ((size_t)bz*COUT + co)*TDIM + t0 + tl);
            outc[((size_t)bz*COUT + co)*TDIM + t0 + tl] = v;
        }
        return;
    }
    if (OUTMODE == 3) {
        size_t abase = (((size_t)bz*CHOUT + sec)*544 + 16 + t0)*64;
        for (int i = tid; i < 64*256; i += 256) {
            int cl = i & 63, tl = i >> 6;
            float v = stage[cl*261 + tl] + __ldg(bias + sec*64 + cl);
            v = gelu1(v);
            __nv_bfloat16 h = __float2bfloat16(v);
            oAh[abase + (size_t)tl*64 + cl] = h;
            oAl[abase + (size_t)tl*64 + cl] = __float2bfloat16(v - __bfloat162float(h));
        }
        return;
    }
    // OUTMODE 1 / 4: add bias (+res) in-place first (coalesced res reads)
    for (int i = tid; i < 64*256; i += 256) {
        int cl = i >> 8, tl = i & 255;
        int co = sec*64 + cl;
        float v = stage[cl*261 + tl] + __ldg(bias + co);
        if (RES) v += __ldg(res + ((size_t)bz*COUT + co)*TDIM + t0 + tl);
        stage[cl*261 + tl] = v;
    }
    __syncthreads();
    if (OUTMODE == 1 && bz < 256) {
        int slice = (int)(bz >> 7), b = (int)(bz & 127);
        float* dst = outt + (((size_t)slice*BT) + (size_t)b*TDIM + t0)*DOUT + sec*64;
        for (int i = tid; i < 256*64; i += 256) {
            int tl = i >> 6, cl = i & 63;
            dst[(size_t)tl*DOUT + cl] = stage[cl*261 + tl];
        }
    } else if (OUTMODE == 1) {
        // slice 2 -> raw A h/l for the dense head
        size_t abase = ((((size_t)bz - 256)*CHOUT + sec)*544 + 16 + t0)*64;
        for (int i = tid; i < 64*256; i += 256) {
            int cl = i & 63, tl = i >> 6;
            float v = stage[cl*261 + tl];
            __nv_bfloat16 h = __float2bfloat16(v);
            oAh[abase + (size_t)tl*64 + cl] = h;
            oAl[abase + (size_t)tl*64 + cl] = __float2bfloat16(v - __bfloat162float(h));
        }
    } else {
        // OUTMODE 4: raw A (oAh2/l2) + gelu A (oAh/l)
        size_t abase = (((size_t)bz*CHOUT + sec)*544 + 16 + t0)*64;
        for (int i = tid; i < 64*256; i += 256) {
            int cl = i & 63, tl = i >> 6;
            float v = stage[cl*261 + tl];
            __nv_bfloat16 h = __float2bfloat16(v);
            oAh2[abase + (size_t)tl*64 + cl] = h;
            oAl2[abase + (size_t)tl*64 + cl] = __float2bfloat16(v - __bfloat162float(h));
            float gv = gelu1(v);
            __nv_bfloat16 gh = __float2bfloat16(gv);
            oAh[abase + (size_t)tl*64 + cl] = gh;
            oAl[abase + (size_t)tl*64 + cl] = __float2bfloat16(gv - __bfloat162float(gh));
        }
    }
}

// ---- reduce 20 dense partials + b2 -> interp ----
__global__ void reduce_kernel(const float* __restrict__ part,
                              const float* __restrict__ b2,
                              float* __restrict__ interp) {
    int i = blockIdx.x * 256 + threadIdx.x;
    if (i >= BT * DIN) return;
    float s = b2[i % 12];
#pragma unroll
    for (int sec = 0; sec < 20; sec++) s += part[(size_t)sec*BT*DIN + i];
    interp[i] = s;
}

// ---- finale: outputs + masks + passthrough (GRU provably dead: mask1==1) ---
__global__ void finale_kernel(const float* __restrict__ interp,
                              const float* __restrict__ M12, const float* __restrict__ c12,
                              const float* __restrict__ x1, const float* __restrict__ x2,
                              float* __restrict__ o1, float* __restrict__ o2,
                              float* __restrict__ om1, float* __restrict__ om2,
                              float* __restrict__ ox1, float* __restrict__ ox2) {
    int r = blockIdx.x * blockDim.x + threadIdx.x;
    if (r >= BT) return;
    float xv[12];
#pragma unroll
    for (int i = 0; i < 12; i++) xv[i] = interp[r * 12 + i];
#pragma unroll
    for (int j = 0; j < 12; j++) {
        float s = c12[j];
#pragma unroll
        for (int i = 0; i < 12; i++) s += xv[i] * M12[i * 12 + j];
        o1[r * 12 + j] = s;
        o2[r * 12 + j] = s;
    }
#pragma unroll
    for (int j = 0; j < 12; j++) {
        float a = x1[r * 12 + j], b = x2[r * 12 + j];
        om1[r * 12 + j] = (a != 0.f) ? 1.f : 0.f;
        om2[r * 12 + j] = (b != 0.f) ? 1.f : 0.f;
        ox1[r * 12 + j] = a;
        ox2[r * 12 + j] = b;
    }
}

// ---------------- host ----------------
#define SMEM_MMA 111744

extern "C" void kernel_launch(void* const* d_in, const int* in_sizes, int n_in,
                              void* d_out, int out_size) {
    const float* x1 = (const float*)d_in[0];
    const float* x2 = (const float*)d_in[1];
    const float* X1 = (const float*)d_in[2];
    const float* X2 = (const float*)d_in[3];
    const float* w_in = (const float*)d_in[5];
    const float* b_in = (const float*)d_in[6];
    const float* c0_1_w = (const float*)d_in[7];
    const float* c0_1_b = (const float*)d_in[8];
    const float* c0_2_w = (const float*)d_in[9];
    const float* c0_2_b = (const float*)d_in[10];
    const float* c1_p_w = (const float*)d_in[11];
    const float* c1_p_b = (const float*)d_in[12];
    const float* c1_1_w = (const float*)d_in[13];
    const float* c1_1_b = (const float*)d_in[14];
    const float* c1_2_w = (const float*)d_in[15];
    const float* c1_2_b = (const float*)d_in[16];
    const float* ih_dense_w = (const float*)d_in[17];
    const float* ih_dense_b = (const float*)d_in[18];
    const float* ih_proj_w = (const float*)d_in[19];
    const float* ih_proj_b = (const float*)d_in[20];
    const float* fc_w = (const float*)d_in[21];
    const float* fc_b = (const float*)d_in[22];
    const float* fcr_w = (const float*)d_in[29];
    const float* fcr_b = (const float*)d_in[30];

    float *b64a, *b320a, *interp, *part, *M12, *c12;
    __nv_bfloat16 *Aga_h, *Aga_l, *Agb_h, *Agb_l, *Ang_h, *Ang_l;
    __nv_bfloat16 *A320h, *A320l, *A320h2, *A320l2, *img;
    cudaGetSymbolAddress((void**)&b64a, g_b64_a);
    cudaGetSymbolAddress((void**)&b320a, g_b320_a);
    cudaGetSymbolAddress((void**)&interp, g_interp);
    cudaGetSymbolAddress((void**)&part, g_part);
    cudaGetSymbolAddress((void**)&M12, g_M12);
    cudaGetSymbolAddress((void**)&c12, g_c12);
    cudaGetSymbolAddress((void**)&Aga_h, g_Aga_h);
    cudaGetSymbolAddress((void**)&Aga_l, g_Aga_l);
    cudaGetSymbolAddress((void**)&Agb_h, g_Agb_h);
    cudaGetSymbolAddress((void**)&Agb_l, g_Agb_l);
    cudaGetSymbolAddress((void**)&Ang_h, g_Ang_h);
    cudaGetSymbolAddress((void**)&Ang_l, g_Ang_l);
    cudaGetSymbolAddress((void**)&A320h, g_A320h);
    cudaGetSymbolAddress((void**)&A320l, g_A320l);
    cudaGetSymbolAddress((void**)&A320h2, g_A320h2);
    cudaGetSymbolAddress((void**)&A320l2, g_A320l2);
    cudaGetSymbolAddress((void**)&img, g_img);

    cudaFuncSetAttribute(conv_mma_kernel<64,64,3,1,false,3>,
                         cudaFuncAttributeMaxDynamicSharedMemorySize, SMEM_MMA);
    cudaFuncSetAttribute(conv_mma_kernel<64,64,3,1,true,4>,
                         cudaFuncAttributeMaxDynamicSharedMemorySize, SMEM_MMA);
    cudaFuncSetAttribute(conv_mma_kernel<64,320,1,1,false,0>,
                         cudaFuncAttributeMaxDynamicSharedMemorySize, SMEM_MMA);
    cudaFuncSetAttribute(conv_mma_kernel<64,320,3,2,false,3>,
                         cudaFuncAttributeMaxDynamicSharedMemorySize, SMEM_MMA);
    cudaFuncSetAttribute(conv_mma_kernel<320,320,3,2,true,1>,
                         cudaFuncAttributeMaxDynamicSharedMemorySize, SMEM_MMA);
    cudaFuncSetAttribute(conv_mma_kernel<320,1280,1,1,false,2>,
                         cudaFuncAttributeMaxDynamicSharedMemorySize, SMEM_MMA);

    float* out = (float*)d_out;
    float* o_o1  = out + 2 * (size_t)BT * DOUT;
    float* o_o2  = o_o1 + (size_t)BT * DIN;
    float* o_m1  = o_o2 + (size_t)BT * DIN;
    float* o_m2  = o_m1 + (size_t)BT * DIN;
    float* o_x1  = o_m2 + (size_t)BT * DIN;
    float* o_x2  = o_x1 + (size_t)BT * DIN;

    setup_kernel<<<3216, 256>>>(c0_1_w, c0_2_w, c1_p_w, c1_1_w, c1_2_w, ih_dense_w,
                                fc_w, fc_b, fcr_w, fcr_b, M12, c12);
    // proj -> f32 residual + gelu A (conv01 input)
    proj_in3_kernel<<<dim3(4, NB), 128>>>(X1, X2, x1, w_in, b_in, b64a, Aga_h, Aga_l);

    // block0
    conv_mma_kernel<64,64,3,1,false,3><<<dim3(2,1,NB), 256, SMEM_MMA>>>(
        Aga_h, Aga_l, img, c0_1_b, nullptr, nullptr, nullptr, nullptr, nullptr,
        Agb_h, Agb_l, nullptr, nullptr);
    conv_mma_kernel<64,64,3,1,true,4><<<dim3(2,1,NB), 256, SMEM_MMA>>>(
        Agb_h, Agb_l, img + (size_t)3*9216, c0_2_b, b64a, nullptr, nullptr, nullptr, nullptr,
        Aga_h, Aga_l, Ang_h, Ang_l);
    // block1
    conv_mma_kernel<64,320,1,1,false,0><<<dim3(2,5,NB), 256, SMEM_MMA>>>(
        Ang_h, Ang_l, img + (size_t)6*9216, c1_p_b, nullptr, b320a, nullptr, nullptr, nullptr,
        nullptr, nullptr, nullptr, nullptr);
    conv_mma_kernel<64,320,3,2,false,3><<<dim3(2,5,NB), 256, SMEM_MMA>>>(
        Aga_h, Aga_l, img + (size_t)11*9216, c1_1_b, nullptr, nullptr, nullptr, nullptr, nullptr,
        A320h, A320l, nullptr, nullptr);
    conv_mma_kernel<320,320,3,2,true,1><<<dim3(2,5,NB), 256, SMEM_MMA>>>(
        A320h, A320l, img + (size_t)26*9216, c1_2_b, b320a, nullptr, out, nullptr, nullptr,
        A320h2, A320l2, nullptr, nullptr);
    // dense head on slice 2 (dense2 fused into epilogue -> partials)
    conv_mma_kernel<320,1280,1,1,false,2><<<dim3(2,20,BB), 256, SMEM_MMA>>>(
        A320h2, A320l2, img + (size_t)101*9216, ih_dense_b, nullptr,
        nullptr, nullptr, ih_proj_w, part, nullptr, nullptr, nullptr, nullptr);
    reduce_kernel<<<(BT*DIN + 255)/256, 256>>>(part, ih_proj_b, interp);
    finale_kernel<<<(BT + 127) / 128, 128>>>(interp, M12, c12, x1, x2,
                                             o_o1, o_o2, o_m1, o_m2, o_x1, o_x2);
}

// round 14
// speedup vs baseline: 1.9384x; 1.0555x over previous
#include <cuda_runtime.h>
#include <cuda_bf16.h>
#include <math.h>
#include <stdint.h>

#define BB 128
#define NB 384
#define TDIM 512
#define DIN 12
#define HH 64
#define DOUT 320
#define BT (BB*TDIM)

// ---------------- static scratch ----------------
__device__ float g_b64_a[(size_t)NB*HH*TDIM];     // proj f32 (residual for conv02)
__device__ float g_interp[BT*DIN];
__device__ float g_part[(size_t)20*BT*DIN];
__device__ float g_M12[144];
__device__ float g_c12[12];
__device__ float g_bias12[DOUT];                  // c1_2_b + c1_p_b
// A-format activations: [bz][ch][544 rows (16 pad | 512 | 16 pad)][64 ci] bf16
// pads never written -> stay zero from static init
__device__ __align__(16) __nv_bfloat16 g_Aga_h[(size_t)NB*544*64];  // gelu buf A
__device__ __align__(16) __nv_bfloat16 g_Aga_l[(size_t)NB*544*64];
__device__ __align__(16) __nv_bfloat16 g_Agb_h[(size_t)NB*544*64];  // gelu buf B
__device__ __align__(16) __nv_bfloat16 g_Agb_l[(size_t)NB*544*64];
__device__ __align__(16) __nv_bfloat16 g_Ang_h[(size_t)NB*544*64];  // non-gelu
__device__ __align__(16) __nv_bfloat16 g_Ang_l[(size_t)NB*544*64];
__device__ __align__(16) __nv_bfloat16 g_A320h[(size_t)NB*5*544*64];
__device__ __align__(16) __nv_bfloat16 g_A320l[(size_t)NB*5*544*64];
__device__ __align__(16) __nv_bfloat16 g_A320h2[(size_t)BB*5*544*64];
__device__ __align__(16) __nv_bfloat16 g_A320l2[(size_t)BB*5*544*64];
// weight images: 201 blocks of [hl 2][n 64][k 72] bf16 (9216 elems each)
// layout: [0,3) conv01 | [3,6) conv02 | [6,86) conv12+c1p (sec*16+it, it=15 is
// c1p) | [86,101) conv11 | [101,201) dense
__device__ __align__(16) __nv_bfloat16 g_img[(size_t)201*9216];

// ---------------- helpers ----------------
__device__ __forceinline__ uint32_t s2u(const void* p) {
    uint32_t a;
    asm("{ .reg .u64 t; cvta.to.shared.u64 t, %1; cvt.u32.u64 %0, t; }" : "=r"(a) : "l"(p));
    return a;
}
__device__ __forceinline__ void cp16(uint32_t d, const void* s) {
    asm volatile("cp.async.cg.shared.global [%0], [%1], 16;" :: "r"(d), "l"(s));
}
#define CP_COMMIT() asm volatile("cp.async.commit_group;" ::: "memory")
#define CP_WAIT1()  asm volatile("cp.async.wait_group 1;" ::: "memory")
#define CP_WAIT0()  asm volatile("cp.async.wait_group 0;" ::: "memory")

__device__ __forceinline__ void mma16816(float* c, const uint32_t* a, const uint32_t* b) {
    asm volatile(
        "mma.sync.aligned.m16n8k16.row.col.f32.bf16.bf16.f32 "
        "{%0,%1,%2,%3}, {%4,%5,%6,%7}, {%8,%9}, {%0,%1,%2,%3};"
        : "+f"(c[0]), "+f"(c[1]), "+f"(c[2]), "+f"(c[3])
        : "r"(a[0]), "r"(a[1]), "r"(a[2]), "r"(a[3]), "r"(b[0]), "r"(b[1]));
}
__device__ __forceinline__ float gelu1(float x) {
    return 0.5f * x * (1.0f + erff(x * 0.7071067811865476f));
}

// ---------------- setup: weight images (hi/lo bf16) + M12 + bias12 ----------
__global__ void setup_kernel(
    const float* __restrict__ c01w, const float* __restrict__ c02w,
    const float* __restrict__ c1pw, const float* __restrict__ c11w,
    const float* __restrict__ c12w, const float* __restrict__ dw,
    const float* __restrict__ fc_w, const float* __restrict__ fc_b,
    const float* __restrict__ fcr_w, const float* __restrict__ fcr_b,
    const float* __restrict__ c12b, const float* __restrict__ c1pb,
    float* __restrict__ M12, float* __restrict__ c12, float* __restrict__ bias12)
{
    const int TOT = 201 * 4096;
    int stride = gridDim.x * 256;
    for (int i = blockIdx.x*256 + threadIdx.x; i < TOT; i += stride) {
        int blk = i >> 12, e = i & 4095;
        int n = e >> 6, k = e & 63;
        float w;
        if (blk < 3) {
            w = c01w[(n*64 + k)*3 + blk];
        } else if (blk < 6) {
            w = c02w[(n*64 + k)*3 + (blk - 3)];
        } else if (blk < 86) {
            int r = blk - 6, sec = r >> 4, it = r & 15;
            if (it < 15) {
                int ch = it / 3, tap = it % 3;
                w = c12w[((sec*64 + n)*320 + ch*64 + k)*3 + tap];
            } else {
                w = c1pw[(sec*64 + n)*64 + k];
            }
        } else if (blk < 101) {
            int r = blk - 86, sec = r/3, tap = r%3;
            w = c11w[((sec*64 + n)*64 + k)*3 + tap];
        } else {
            int r = blk - 101, s = r/5, ch = r%5;
            w = dw[(ch*64 + k)*1280 + s*64 + n];
        }
        size_t base = (size_t)blk * 9216;
        uint32_t idx = (uint32_t)n * 72 + (uint32_t)k;
        __nv_bfloat16 h = __float2bfloat16(w);
        g_img[base + idx] = h;
        g_img[base + 4608 + idx] = __float2bfloat16(w - __bfloat162float(h));
    }
    if (blockIdx.x == 0) {
        int tid = threadIdx.x;
        if (tid < 144) {
            int a = tid / 12, bj = tid % 12;
            float s = 0.f;
            for (int k = 0; k < DOUT; k++) s += fc_w[a*DOUT + k] * fcr_w[k*12 + bj];
            M12[tid] = s;
        } else if (tid < 156) {
            int bj = tid - 144;
            float s = fcr_b[bj];
            for (int k = 0; k < DOUT; k++) s += fc_b[k] * fcr_w[k*12 + bj];
            c12[bj] = s;
        }
    }
    if (blockIdx.x == 1) {
        for (int c = threadIdx.x; c < DOUT; c += 256)
            bias12[c] = c12b[c] + c1pb[c];
    }
}

// ---------------- input projection, all 3 slices; writes f32 + gelu A --------
__global__ void proj_in3_kernel(const float* __restrict__ X1, const float* __restrict__ X2,
                                const float* __restrict__ x1,
                                const float* __restrict__ w, const float* __restrict__ bi,
                                float* __restrict__ outf,
                                __nv_bfloat16* __restrict__ oAh,
                                __nv_bfloat16* __restrict__ oAl) {
    int bz = blockIdx.y;
    int slice = bz >> 7, b = bz & 127;
    const float* x = (slice == 0) ? X1 : (slice == 1) ? X2 : x1;
    int t = blockIdx.x * 128 + threadIdx.x;
    float xv[DIN];
#pragma unroll
    for (int i = 0; i < DIN; i++) xv[i] = x[(b * TDIM + t) * DIN + i];
    size_t abase = ((size_t)bz * 544 + 16 + t) * 64;
    for (int c = 0; c < HH; c++) {
        float s = bi[c];
#pragma unroll
        for (int i = 0; i < DIN; i++) s += xv[i] * w[i * HH + c];
        outf[((size_t)bz * HH + c) * TDIM + t] = s;
        float gv = gelu1(s);
        __nv_bfloat16 h = __float2bfloat16(gv);
        oAh[abase + c] = h;
        oAl[abase + c] = __float2bfloat16(gv - __bfloat162float(h));
    }
}

// ---------------- tensor-core conv via mma.sync (split bf16, 3-pass) --------
// CTA tile M=256 x N=64; 8 warps (4M x 2N), warp tile 64x32.
// RC: append one extra iteration (A = gA2 raw block0 output, shift 0) that
//     accumulates the 1x1 projection residual directly into the acc.
// OUTMODE: 1 = conv12: slices 0/1 transposed f32 to d_out; slice 2 raw A h/l
//          2 = dense head (relu + W2 partial to g_part)
//          3 = gelu A h/l (+bias)
//          4 = conv02: raw A h/l (oAh2/l2) AND gelu A h/l (oAh/l), +bias+res
template<int CIN, int COUT, int TAPS, int DIL, bool RES, int OUTMODE, bool RC>
__global__ __launch_bounds__(256, 2) void conv_mma_kernel(
    const __nv_bfloat16* __restrict__ gAh, const __nv_bfloat16* __restrict__ gAl,
    const __nv_bfloat16* __restrict__ gA2h, const __nv_bfloat16* __restrict__ gA2l,
    const __nv_bfloat16* __restrict__ img,
    const float* __restrict__ bias, const float* __restrict__ res,
    float* __restrict__ outt,
    const float* __restrict__ W2, float* __restrict__ part,
    __nv_bfloat16* __restrict__ oAh, __nv_bfloat16* __restrict__ oAl,
    __nv_bfloat16* __restrict__ oAh2, __nv_bfloat16* __restrict__ oAl2)
{
    constexpr int CHUNKS = CIN / 64;
    constexpr int CHOUT = COUT / 64;
    constexpr int NIT = CHUNKS * TAPS + (RC ? 1 : 0);
    extern __shared__ __align__(16) char smem[];
    uint32_t sb = s2u(smem);

    int tid = threadIdx.x, lane = tid & 31, wid = tid >> 5;
    int g = lane >> 2, q = lane & 3;
    int wm = wid >> 1, wn = wid & 1;
    size_t bz = blockIdx.z;
    int t0 = blockIdx.x * 256, sec = blockIdx.y;

    float acc[4][4][4];
#pragma unroll
    for (int a = 0; a < 4; a++)
#pragma unroll
        for (int b = 0; b < 4; b++)
#pragma unroll
            for (int c = 0; c < 4; c++) acc[a][b][c] = 0.f;

    // A: [0, 74880) single buffer (hi 37440 | lo 37440), 260 rows x 72 stride
    // B: [74880, 111744) two buffers of 18432
    auto loadA = [&](const __nv_bfloat16* srcH, const __nv_bfloat16* srcL,
                     size_t rowbase) {
        for (int i = tid; i < 4160; i += 256) {
            int hl = (i >= 2080) ? 1 : 0;
            int rr = i - hl * 2080;
            int r = rr >> 3, c = rr & 7;
            const __nv_bfloat16* gsrc = (hl ? srcL : srcH) + (rowbase + r) * 64 + c * 8;
            cp16(sb + hl*37440 + r*144 + c*16, gsrc);
        }
    };
    auto loadB = [&](int it2, int slot) {
        const char* gsrc = (const char*)(img + ((size_t)sec * NIT + it2) * 9216);
        for (int i = tid; i < 1152; i += 256)
            cp16(sb + 74880 + slot*18432 + i*16, gsrc + i*16);
    };

    loadB(0, 0);
    CP_COMMIT();

    for (int it = 0; it < NIT; it++) {
        int shift;
        bool nc;
        bool rcit = RC && (it == CHUNKS * TAPS);
        if (rcit) { shift = 0; nc = true; }
        else {
            int tap = it % TAPS;
            shift = (tap - (TAPS - 1) / 2) * DIL;
            nc = (tap == 0);
        }
        __syncthreads();     // prior compute done: A buffer / B slot safe
        if (nc) {
            if (rcit) loadA(gA2h, gA2l, (size_t)bz * 544 + (16 + t0 - 2));
            else      loadA(gAh, gAl, ((size_t)bz * CHUNKS + it / TAPS) * 544 + (16 + t0 - 2));
            CP_COMMIT();
        }
        if (it + 1 < NIT) {
            loadB(it + 1, (it + 1) & 1);
            CP_COMMIT();
            CP_WAIT1();      // A (if any) + B(it) complete; B(it+1) in flight
        } else {
            CP_WAIT0();
        }
        __syncthreads();
        const __nv_bfloat16* sAh = (const __nv_bfloat16*)smem;
        const __nv_bfloat16* sAl = sAh + 18720;
        const __nv_bfloat16* sBh = (const __nv_bfloat16*)(smem + 74880 + (it & 1)*18432);
        const __nv_bfloat16* sBl = sBh + 4608;
        int rb = 2 + shift + wm*64 + g;
#pragma unroll
        for (int ks = 0; ks < 4; ks++) {
            int kc = ks*16 + q*2;
            uint32_t ah[4][4], al[4][4], bh[4][2], bl[4][2];
#pragma unroll
            for (int mt = 0; mt < 4; mt++) {
                int base = (rb + mt*16)*72 + kc;
                ah[mt][0] = *(const uint32_t*)(sAh + base);
                ah[mt][1] = *(const uint32_t*)(sAh + base + 8*72);
                ah[mt][2] = *(const uint32_t*)(sAh + base + 8);
                ah[mt][3] = *(const uint32_t*)(sAh + base + 8*72 + 8);
                al[mt][0] = *(const uint32_t*)(sAl + base);
                al[mt][1] = *(const uint32_t*)(sAl + base + 8*72);
                al[mt][2] = *(const uint32_t*)(sAl + base + 8);
                al[mt][3] = *(const uint32_t*)(sAl + base + 8*72 + 8);
            }
#pragma unroll
            for (int nt = 0; nt < 4; nt++) {
                int nb = (wn*32 + nt*8 + g)*72 + kc;
                bh[nt][0] = *(const uint32_t*)(sBh + nb);
                bh[nt][1] = *(const uint32_t*)(sBh + nb + 8);
                bl[nt][0] = *(const uint32_t*)(sBl + nb);
                bl[nt][1] = *(const uint32_t*)(sBl + nb + 8);
            }
#pragma unroll
            for (int mt = 0; mt < 4; mt++)
#pragma unroll
                for (int nt = 0; nt < 4; nt++) {
                    mma16816(acc[mt][nt], ah[mt], bh[nt]);
                    mma16816(acc[mt][nt], al[mt], bh[nt]);
                    mma16816(acc[mt][nt], ah[mt], bl[nt]);
                }
        }
    }
    // -------- epilogue --------
    __syncthreads();
    float* stage = (float*)smem;          // [n 64][m 256] at stride 261 (odd)
#pragma unroll
    for (int mt = 0; mt < 4; mt++)
#pragma unroll
        for (int nt = 0; nt < 4; nt++) {
            int m = wm*64 + mt*16 + g;
            int n = wn*32 + nt*8 + q*2;
            stage[n*261 + m]         = acc[mt][nt][0];
            stage[(n+1)*261 + m]     = acc[mt][nt][1];
            stage[n*261 + m + 8]     = acc[mt][nt][2];
            stage[(n+1)*261 + m + 8] = acc[mt][nt][3];
        }
    __syncthreads();

    if (OUTMODE == 2) {
        float* sW2 = (float*)(smem + 67072);   // 64*12 f32
        float* sB1 = sW2 + 64*12;              // 64 f32
        for (int i = tid; i < 64*12; i += 256)
            sW2[i] = __ldg(W2 + (sec*64 + i/12)*12 + (i%12));
        if (tid < 64) sB1[tid] = __ldg(bias + sec*64 + tid);
        __syncthreads();
        for (int i = tid; i < 256*12; i += 256) {
            int tl = i / 12, o = i % 12;
            float s = 0.f;
#pragma unroll 8
            for (int cl = 0; cl < 64; cl++) {
                float v = stage[cl*261 + tl] + sB1[cl];
                v = v > 0.f ? v : 0.f;
                s += v * sW2[cl*12 + o];
            }
            part[((size_t)sec*BT + bz*TDIM + t0 + tl)*12 + o] = s;
        }
        return;
    }

    if (OUTMODE == 3) {
        size_t abase = (((size_t)bz*CHOUT + sec)*544 + 16 + t0)*64;
        for (int i = tid; i < 64*256; i += 256) {
            int cl = i & 63, tl = i >> 6;
            float v = stage[cl*261 + tl] + __ldg(bias + sec*64 + cl);
            v = gelu1(v);
            __nv_bfloat16 h = __float2bfloat16(v);
            oAh[abase + (size_t)tl*64 + cl] = h;
            oAl[abase + (size_t)tl*64 + cl] = __float2bfloat16(v - __bfloat162float(h));
        }
        return;
    }
    // OUTMODE 1 / 4: add bias (+res) in-place first (coalesced res reads)
    for (int i = tid; i < 64*256; i += 256) {
        int cl = i >> 8, tl = i & 255;
        int co = sec*64 + cl;
        float v = stage[cl*261 + tl] + __ldg(bias + co);
        if (RES) v += __ldg(res + ((size_t)bz*COUT + co)*TDIM + t0 + tl);
        stage[cl*261 + tl] = v;
    }
    __syncthreads();
    if (OUTMODE == 1 && bz < 256) {
        int slice = (int)(bz >> 7), b = (int)(bz & 127);
        float* dst = outt + (((size_t)slice*BT) + (size_t)b*TDIM + t0)*DOUT + sec*64;
        for (int i = tid; i < 256*64; i += 256) {
            int tl = i >> 6, cl = i & 63;
            dst[(size_t)tl*DOUT + cl] = stage[cl*261 + tl];
        }
    } else if (OUTMODE == 1) {
        // slice 2 -> raw A h/l for the dense head
        size_t abase = ((((size_t)bz - 256)*CHOUT + sec)*544 + 16 + t0)*64;
        for (int i = tid; i < 64*256; i += 256) {
            int cl = i & 63, tl = i >> 6;
            float v = stage[cl*261 + tl];
            __nv_bfloat16 h = __float2bfloat16(v);
            oAh[abase + (size_t)tl*64 + cl] = h;
            oAl[abase + (size_t)tl*64 + cl] = __float2bfloat16(v - __bfloat162float(h));
        }
    } else {
        // OUTMODE 4: raw A (oAh2/l2) + gelu A (oAh/l)
        size_t abase = (((size_t)bz*CHOUT + sec)*544 + 16 + t0)*64;
        for (int i = tid; i < 64*256; i += 256) {
            int cl = i & 63, tl = i >> 6;
            float v = stage[cl*261 + tl];
            __nv_bfloat16 h = __float2bfloat16(v);
            oAh2[abase + (size_t)tl*64 + cl] = h;
            oAl2[abase + (size_t)tl*64 + cl] = __float2bfloat16(v - __bfloat162float(h));
            float gv = gelu1(v);
            __nv_bfloat16 gh = __float2bfloat16(gv);
            oAh[abase + (size_t)tl*64 + cl] = gh;
            oAl[abase + (size_t)tl*64 + cl] = __float2bfloat16(gv - __bfloat162float(gh));
        }
    }
}

// ---- reduce 20 dense partials + b2 -> interp ----
__global__ void reduce_kernel(const float* __restrict__ part,
                              const float* __restrict__ b2,
                              float* __restrict__ interp) {
    int i = blockIdx.x * 256 + threadIdx.x;
    if (i >= BT * DIN) return;
    float s = b2[i % 12];
#pragma unroll
    for (int sec = 0; sec < 20; sec++) s += part[(size_t)sec*BT*DIN + i];
    interp[i] = s;
}

// ---- finale: outputs + masks + passthrough (GRU provably dead: mask1==1) ---
__global__ void finale_kernel(const float* __restrict__ interp,
                              const float* __restrict__ M12, const float* __restrict__ c12,
                              const float* __restrict__ x1, const float* __restrict__ x2,
                              float* __restrict__ o1, float* __restrict__ o2,
                              float* __restrict__ om1, float* __restrict__ om2,
                              float* __restrict__ ox1, float* __restrict__ ox2) {
    int r = blockIdx.x * blockDim.x + threadIdx.x;
    if (r >= BT) return;
    float xv[12];
#pragma unroll
    for (int i = 0; i < 12; i++) xv[i] = interp[r * 12 + i];
#pragma unroll
    for (int j = 0; j < 12; j++) {
        float s = c12[j];
#pragma unroll
        for (int i = 0; i < 12; i++) s += xv[i] * M12[i * 12 + j];
        o1[r * 12 + j] = s;
        o2[r * 12 + j] = s;
    }
#pragma unroll
    for (int j = 0; j < 12; j++) {
        float a = x1[r * 12 + j], b = x2[r * 12 + j];
        om1[r * 12 + j] = (a != 0.f) ? 1.f : 0.f;
        om2[r * 12 + j] = (b != 0.f) ? 1.f : 0.f;
        ox1[r * 12 + j] = a;
        ox2[r * 12 + j] = b;
    }
}

// ---------------- host ----------------
#define SMEM_MMA 111744

extern "C" void kernel_launch(void* const* d_in, const int* in_sizes, int n_in,
                              void* d_out, int out_size) {
    const float* x1 = (const float*)d_in[0];
    const float* x2 = (const float*)d_in[1];
    const float* X1 = (const float*)d_in[2];
    const float* X2 = (const float*)d_in[3];
    const float* w_in = (const float*)d_in[5];
    const float* b_in = (const float*)d_in[6];
    const float* c0_1_w = (const float*)d_in[7];
    const float* c0_1_b = (const float*)d_in[8];
    const float* c0_2_w = (const float*)d_in[9];
    const float* c0_2_b = (const float*)d_in[10];
    const float* c1_p_w = (const float*)d_in[11];
    const float* c1_p_b = (const float*)d_in[12];
    const float* c1_1_w = (const float*)d_in[13];
    const float* c1_1_b = (const float*)d_in[14];
    const float* c1_2_w = (const float*)d_in[15];
    const float* c1_2_b = (const float*)d_in[16];
    const float* ih_dense_w = (const float*)d_in[17];
    const float* ih_dense_b = (const float*)d_in[18];
    const float* ih_proj_w = (const float*)d_in[19];
    const float* ih_proj_b = (const float*)d_in[20];
    const float* fc_w = (const float*)d_in[21];
    const float* fc_b = (const float*)d_in[22];
    const float* fcr_w = (const float*)d_in[29];
    const float* fcr_b = (const float*)d_in[30];

    float *b64a, *interp, *part, *M12, *c12, *bias12;
    __nv_bfloat16 *Aga_h, *Aga_l, *Agb_h, *Agb_l, *Ang_h, *Ang_l;
    __nv_bfloat16 *A320h, *A320l, *A320h2, *A320l2, *img;
    cudaGetSymbolAddress((void**)&b64a, g_b64_a);
    cudaGetSymbolAddress((void**)&interp, g_interp);
    cudaGetSymbolAddress((void**)&part, g_part);
    cudaGetSymbolAddress((void**)&M12, g_M12);
    cudaGetSymbolAddress((void**)&c12, g_c12);
    cudaGetSymbolAddress((void**)&bias12, g_bias12);
    cudaGetSymbolAddress((void**)&Aga_h, g_Aga_h);
    cudaGetSymbolAddress((void**)&Aga_l, g_Aga_l);
    cudaGetSymbolAddress((void**)&Agb_h, g_Agb_h);
    cudaGetSymbolAddress((void**)&Agb_l, g_Agb_l);
    cudaGetSymbolAddress((void**)&Ang_h, g_Ang_h);
    cudaGetSymbolAddress((void**)&Ang_l, g_Ang_l);
    cudaGetSymbolAddress((void**)&A320h, g_A320h);
    cudaGetSymbolAddress((void**)&A320l, g_A320l);
    cudaGetSymbolAddress((void**)&A320h2, g_A320h2);
    cudaGetSymbolAddress((void**)&A320l2, g_A320l2);
    cudaGetSymbolAddress((void**)&img, g_img);

    cudaFuncSetAttribute(conv_mma_kernel<64,64,3,1,false,3,false>,
                         cudaFuncAttributeMaxDynamicSharedMemorySize, SMEM_MMA);
    cudaFuncSetAttribute(conv_mma_kernel<64,64,3,1,true,4,false>,
                         cudaFuncAttributeMaxDynamicSharedMemorySize, SMEM_MMA);
    cudaFuncSetAttribute(conv_mma_kernel<64,320,3,2,false,3,false>,
                         cudaFuncAttributeMaxDynamicSharedMemorySize, SMEM_MMA);
    cudaFuncSetAttribute(conv_mma_kernel<320,320,3,2,false,1,true>,
                         cudaFuncAttributeMaxDynamicSharedMemorySize, SMEM_MMA);
    cudaFuncSetAttribute(conv_mma_kernel<320,1280,1,1,false,2,false>,
                         cudaFuncAttributeMaxDynamicSharedMemorySize, SMEM_MMA);

    float* out = (float*)d_out;
    float* o_o1  = out + 2 * (size_t)BT * DOUT;
    float* o_o2  = o_o1 + (size_t)BT * DIN;
    float* o_m1  = o_o2 + (size_t)BT * DIN;
    float* o_m2  = o_m1 + (size_t)BT * DIN;
    float* o_x1  = o_m2 + (size_t)BT * DIN;
    float* o_x2  = o_x1 + (size_t)BT * DIN;

    setup_kernel<<<3216, 256>>>(c0_1_w, c0_2_w, c1_p_w, c1_1_w, c1_2_w, ih_dense_w,
                                fc_w, fc_b, fcr_w, fcr_b, c1_2_b, c1_p_b,
                                M12, c12, bias12);
    // proj -> f32 residual + gelu A (conv01 input)
    proj_in3_kernel<<<dim3(4, NB), 128>>>(X1, X2, x1, w_in, b_in, b64a, Aga_h, Aga_l);

    // block0
    conv_mma_kernel<64,64,3,1,false,3,false><<<dim3(2,1,NB), 256, SMEM_MMA>>>(
        Aga_h, Aga_l, nullptr, nullptr, img, c0_1_b, nullptr, nullptr, nullptr, nullptr,
        Agb_h, Agb_l, nullptr, nullptr);
    conv_mma_kernel<64,64,3,1,true,4,false><<<dim3(2,1,NB), 256, SMEM_MMA>>>(
        Agb_h, Agb_l, nullptr, nullptr, img + (size_t)3*9216, c0_2_b, b64a,
        nullptr, nullptr, nullptr, Aga_h, Aga_l, Ang_h, Ang_l);
    // block1: conv11 (gelu out), then conv12 with fused 1x1 projection residual
    conv_mma_kernel<64,320,3,2,false,3,false><<<dim3(2,5,NB), 256, SMEM_MMA>>>(
        Aga_h, Aga_l, nullptr, nullptr, img + (size_t)86*9216, c1_1_b, nullptr,
        nullptr, nullptr, nullptr, A320h, A320l, nullptr, nullptr);
    conv_mma_kernel<320,320,3,2,false,1,true><<<dim3(2,5,NB), 256, SMEM_MMA>>>(
        A320h, A320l, Ang_h, Ang_l, img + (size_t)6*9216, bias12, nullptr,
        out, nullptr, nullptr, A320h2, A320l2, nullptr, nullptr);
    // dense head on slice 2 (dense2 fused into epilogue -> partials)
    conv_mma_kernel<320,1280,1,1,false,2,false><<<dim3(2,20,BB), 256, SMEM_MMA>>>(
        A320h2, A320l2, nullptr, nullptr, img + (size_t)101*9216, ih_dense_b, nullptr,
        nullptr, ih_proj_w, part, nullptr, nullptr, nullptr, nullptr);
    reduce_kernel<<<(BT*DIN + 255)/256, 256>>>(part, ih_proj_b, interp);
    finale_kernel<<<(BT + 127) / 128, 128>>>(interp, M12, c12, x1, x2,
                                             o_o1, o_o2, o_m1, o_m2, o_x1, o_x2);
}

// round 15
// speedup vs baseline: 2.0662x; 1.0659x over previous
#include <cuda_runtime.h>
#include <cuda_bf16.h>
#include <math.h>
#include <stdint.h>

#define BB 128
#define NB 384
#define TDIM 512
#define DIN 12
#define HH 64
#define DOUT 320
#define BT (BB*TDIM)

// ---------------- static scratch ----------------
__device__ float g_b64_a[(size_t)NB*HH*TDIM];     // proj f32 (residual for conv02)
__device__ float g_interp[BT*DIN];
__device__ float g_part[(size_t)20*BT*DIN];
__device__ float g_M12[144];
__device__ float g_c12[12];
__device__ float g_bias12[DOUT];                  // c1_2_b + c1_p_b
// A-format activations: [bz][ch][544 rows (16 pad | 512 | 16 pad)][64 ci] bf16
// pads never written -> stay zero from static init
__device__ __align__(16) __nv_bfloat16 g_Aga_h[(size_t)NB*544*64];  // gelu buf A
__device__ __align__(16) __nv_bfloat16 g_Aga_l[(size_t)NB*544*64];
__device__ __align__(16) __nv_bfloat16 g_Agb_h[(size_t)NB*544*64];  // gelu buf B
__device__ __align__(16) __nv_bfloat16 g_Agb_l[(size_t)NB*544*64];
__device__ __align__(16) __nv_bfloat16 g_Ang_h[(size_t)NB*544*64];  // non-gelu
__device__ __align__(16) __nv_bfloat16 g_Ang_l[(size_t)NB*544*64];
__device__ __align__(16) __nv_bfloat16 g_A320h[(size_t)NB*5*544*64];
__device__ __align__(16) __nv_bfloat16 g_A320l[(size_t)NB*5*544*64];
__device__ __align__(16) __nv_bfloat16 g_A320h2[(size_t)BB*5*544*64];
__device__ __align__(16) __nv_bfloat16 g_A320l2[(size_t)BB*5*544*64];
// weight images: 201 blocks of [hl 2][n 64][k 72] bf16 (9216 elems each)
// layout: [0,3) conv01 | [3,6) conv02 | [6,86) conv12+c1p (sec*16+it, it=15 is
// c1p) | [86,101) conv11 | [101,201) dense
__device__ __align__(16) __nv_bfloat16 g_img[(size_t)201*9216];

// ---------------- helpers ----------------
__device__ __forceinline__ uint32_t s2u(const void* p) {
    uint32_t a;
    asm("{ .reg .u64 t; cvta.to.shared.u64 t, %1; cvt.u32.u64 %0, t; }" : "=r"(a) : "l"(p));
    return a;
}
__device__ __forceinline__ void cp16(uint32_t d, const void* s) {
    asm volatile("cp.async.cg.shared.global [%0], [%1], 16;" :: "r"(d), "l"(s));
}
#define CP_COMMIT() asm volatile("cp.async.commit_group;" ::: "memory")
#define CP_WAIT1()  asm volatile("cp.async.wait_group 1;" ::: "memory")
#define CP_WAIT0()  asm volatile("cp.async.wait_group 0;" ::: "memory")

__device__ __forceinline__ void mma16816(float* c, const uint32_t* a, const uint32_t* b) {
    asm volatile(
        "mma.sync.aligned.m16n8k16.row.col.f32.bf16.bf16.f32 "
        "{%0,%1,%2,%3}, {%4,%5,%6,%7}, {%8,%9}, {%0,%1,%2,%3};"
        : "+f"(c[0]), "+f"(c[1]), "+f"(c[2]), "+f"(c[3])
        : "r"(a[0]), "r"(a[1]), "r"(a[2]), "r"(a[3]), "r"(b[0]), "r"(b[1]));
}
__device__ __forceinline__ float gelu1(float x) {
    return 0.5f * x * (1.0f + erff(x * 0.7071067811865476f));
}
// pack 4 floats into hi / lo bf16 uint2 pairs
__device__ __forceinline__ void pack4(const float* v, uint2& uh, uint2& ul) {
    __nv_bfloat16 h[4], l[4];
#pragma unroll
    for (int j = 0; j < 4; j++) {
        h[j] = __float2bfloat16(v[j]);
        l[j] = __float2bfloat16(v[j] - __bfloat162float(h[j]));
    }
    uh = *(const uint2*)h;
    ul = *(const uint2*)l;
}

// ---------------- setup: weight images (hi/lo bf16) + M12 + bias12 ----------
__global__ void setup_kernel(
    const float* __restrict__ c01w, const float* __restrict__ c02w,
    const float* __restrict__ c1pw, const float* __restrict__ c11w,
    const float* __restrict__ c12w, const float* __restrict__ dw,
    const float* __restrict__ fc_w, const float* __restrict__ fc_b,
    const float* __restrict__ fcr_w, const float* __restrict__ fcr_b,
    const float* __restrict__ c12b, const float* __restrict__ c1pb,
    float* __restrict__ M12, float* __restrict__ c12, float* __restrict__ bias12)
{
    const int TOT = 201 * 4096;
    int stride = gridDim.x * 256;
    for (int i = blockIdx.x*256 + threadIdx.x; i < TOT; i += stride) {
        int blk = i >> 12, e = i & 4095;
        int n = e >> 6, k = e & 63;
        float w;
        if (blk < 3) {
            w = c01w[(n*64 + k)*3 + blk];
        } else if (blk < 6) {
            w = c02w[(n*64 + k)*3 + (blk - 3)];
        } else if (blk < 86) {
            int r = blk - 6, sec = r >> 4, it = r & 15;
            if (it < 15) {
                int ch = it / 3, tap = it % 3;
                w = c12w[((sec*64 + n)*320 + ch*64 + k)*3 + tap];
            } else {
                w = c1pw[(sec*64 + n)*64 + k];
            }
        } else if (blk < 101) {
            int r = blk - 86, sec = r/3, tap = r%3;
            w = c11w[((sec*64 + n)*64 + k)*3 + tap];
        } else {
            int r = blk - 101, s = r/5, ch = r%5;
            w = dw[(ch*64 + k)*1280 + s*64 + n];
        }
        size_t base = (size_t)blk * 9216;
        uint32_t idx = (uint32_t)n * 72 + (uint32_t)k;
        __nv_bfloat16 h = __float2bfloat16(w);
        g_img[base + idx] = h;
        g_img[base + 4608 + idx] = __float2bfloat16(w - __bfloat162float(h));
    }
    if (blockIdx.x == 0) {
        int tid = threadIdx.x;
        if (tid < 144) {
            int a = tid / 12, bj = tid % 12;
            float s = 0.f;
            for (int k = 0; k < DOUT; k++) s += fc_w[a*DOUT + k] * fcr_w[k*12 + bj];
            M12[tid] = s;
        } else if (tid < 156) {
            int bj = tid - 144;
            float s = fcr_b[bj];
            for (int k = 0; k < DOUT; k++) s += fc_b[k] * fcr_w[k*12 + bj];
            c12[bj] = s;
        }
    }
    if (blockIdx.x == 1) {
        for (int c = threadIdx.x; c < DOUT; c += 256)
            bias12[c] = c12b[c] + c1pb[c];
    }
}

// ---------------- input projection, all 3 slices; writes f32 + gelu A --------
// smem-staged A writes for full coalescing.
__global__ __launch_bounds__(128) void proj_in3_kernel(
    const float* __restrict__ X1, const float* __restrict__ X2,
    const float* __restrict__ x1,
    const float* __restrict__ w, const float* __restrict__ bi,
    float* __restrict__ outf,
    __nv_bfloat16* __restrict__ oAh, __nv_bfloat16* __restrict__ oAl) {
    __shared__ __nv_bfloat16 sh[128*64], sl[128*64];
    int bz = blockIdx.y;
    int slice = bz >> 7, b = bz & 127;
    const float* x = (slice == 0) ? X1 : (slice == 1) ? X2 : x1;
    int tid = threadIdx.x;
    int t0 = blockIdx.x * 128;
    int t = t0 + tid;
    float xv[DIN];
#pragma unroll
    for (int i = 0; i < DIN; i++) xv[i] = x[(b * TDIM + t) * DIN + i];
    for (int c = 0; c < HH; c++) {
        float s = bi[c];
#pragma unroll
        for (int i = 0; i < DIN; i++) s += xv[i] * w[i * HH + c];
        outf[((size_t)bz * HH + c) * TDIM + t] = s;
        float gv = gelu1(s);
        __nv_bfloat16 h = __float2bfloat16(gv);
        sh[tid*64 + c] = h;
        sl[tid*64 + c] = __float2bfloat16(gv - __bfloat162float(h));
    }
    __syncthreads();
    size_t abase = ((size_t)bz * 544 + 16 + t0) * 64;  // 16B-aligned (x64 elems)
    const uint4* s4h = (const uint4*)sh;
    const uint4* s4l = (const uint4*)sl;
    uint4* d4h = (uint4*)(oAh + abase);
    uint4* d4l = (uint4*)(oAl + abase);
    for (int i = tid; i < 1024; i += 128) {
        d4h[i] = s4h[i];
        d4l[i] = s4l[i];
    }
}

// ---------------- tensor-core conv via mma.sync (split bf16, 3-pass) --------
// CTA tile M=256 x N=64; 8 warps (4M x 2N), warp tile 64x32.
// RC: append one extra iteration (A = gA2 raw block0 output, shift 0) that
//     accumulates the 1x1 projection residual directly into the acc.
// OUTMODE: 1 = conv12: slices 0/1 transposed f32 to d_out; slice 2 raw A h/l
//          2 = dense head (relu + W2 partial to g_part)
//          3 = gelu A h/l (+bias)
//          4 = conv02: raw A h/l (oAh2/l2) AND gelu A h/l (oAh/l), +bias+res
template<int CIN, int COUT, int TAPS, int DIL, bool RES, int OUTMODE, bool RC>
__global__ __launch_bounds__(256, 2) void conv_mma_kernel(
    const __nv_bfloat16* __restrict__ gAh, const __nv_bfloat16* __restrict__ gAl,
    const __nv_bfloat16* __restrict__ gA2h, const __nv_bfloat16* __restrict__ gA2l,
    const __nv_bfloat16* __restrict__ img,
    const float* __restrict__ bias, const float* __restrict__ res,
    float* __restrict__ outt,
    const float* __restrict__ W2, float* __restrict__ part,
    __nv_bfloat16* __restrict__ oAh, __nv_bfloat16* __restrict__ oAl,
    __nv_bfloat16* __restrict__ oAh2, __nv_bfloat16* __restrict__ oAl2)
{
    constexpr int CHUNKS = CIN / 64;
    constexpr int CHOUT = COUT / 64;
    constexpr int NIT = CHUNKS * TAPS + (RC ? 1 : 0);
    extern __shared__ __align__(16) char smem[];
    uint32_t sb = s2u(smem);

    int tid = threadIdx.x, lane = tid & 31, wid = tid >> 5;
    int g = lane >> 2, q = lane & 3;
    int wm = wid >> 1, wn = wid & 1;
    size_t bz = blockIdx.z;
    int t0 = blockIdx.x * 256, sec = blockIdx.y;

    float acc[4][4][4];
#pragma unroll
    for (int a = 0; a < 4; a++)
#pragma unroll
        for (int b = 0; b < 4; b++)
#pragma unroll
            for (int c = 0; c < 4; c++) acc[a][b][c] = 0.f;

    // A: [0, 74880) single buffer (hi 37440 | lo 37440), 260 rows x 72 stride
    // B: [74880, 111744) two buffers of 18432
    auto loadA = [&](const __nv_bfloat16* srcH, const __nv_bfloat16* srcL,
                     size_t rowbase) {
        for (int i = tid; i < 4160; i += 256) {
            int hl = (i >= 2080) ? 1 : 0;
            int rr = i - hl * 2080;
            int r = rr >> 3, c = rr & 7;
            const __nv_bfloat16* gsrc = (hl ? srcL : srcH) + (rowbase + r) * 64 + c * 8;
            cp16(sb + hl*37440 + r*144 + c*16, gsrc);
        }
    };
    auto loadB = [&](int it2, int slot) {
        const char* gsrc = (const char*)(img + ((size_t)sec * NIT + it2) * 9216);
        for (int i = tid; i < 1152; i += 256)
            cp16(sb + 74880 + slot*18432 + i*16, gsrc + i*16);
    };

    loadB(0, 0);
    CP_COMMIT();

    for (int it = 0; it < NIT; it++) {
        int shift;
        bool nc;
        bool rcit = RC && (it == CHUNKS * TAPS);
        if (rcit) { shift = 0; nc = true; }
        else {
            int tap = it % TAPS;
            shift = (tap - (TAPS - 1) / 2) * DIL;
            nc = (tap == 0);
        }
        __syncthreads();     // prior compute done: A buffer / B slot safe
        if (nc) {
            if (rcit) loadA(gA2h, gA2l, (size_t)bz * 544 + (16 + t0 - 2));
            else      loadA(gAh, gAl, ((size_t)bz * CHUNKS + it / TAPS) * 544 + (16 + t0 - 2));
            CP_COMMIT();
        }
        if (it + 1 < NIT) {
            loadB(it + 1, (it + 1) & 1);
            CP_COMMIT();
            CP_WAIT1();      // A (if any) + B(it) complete; B(it+1) in flight
        } else {
            CP_WAIT0();
        }
        __syncthreads();
        const __nv_bfloat16* sAh = (const __nv_bfloat16*)smem;
        const __nv_bfloat16* sAl = sAh + 18720;
        const __nv_bfloat16* sBh = (const __nv_bfloat16*)(smem + 74880 + (it & 1)*18432);
        const __nv_bfloat16* sBl = sBh + 4608;
        int rb = 2 + shift + wm*64 + g;
#pragma unroll
        for (int ks = 0; ks < 4; ks++) {
            int kc = ks*16 + q*2;
            uint32_t ah[4][4], al[4][4], bh[4][2], bl[4][2];
#pragma unroll
            for (int mt = 0; mt < 4; mt++) {
                int base = (rb + mt*16)*72 + kc;
                ah[mt][0] = *(const uint32_t*)(sAh + base);
                ah[mt][1] = *(const uint32_t*)(sAh + base + 8*72);
                ah[mt][2] = *(const uint32_t*)(sAh + base + 8);
                ah[mt][3] = *(const uint32_t*)(sAh + base + 8*72 + 8);
                al[mt][0] = *(const uint32_t*)(sAl + base);
                al[mt][1] = *(const uint32_t*)(sAl + base + 8*72);
                al[mt][2] = *(const uint32_t*)(sAl + base + 8);
                al[mt][3] = *(const uint32_t*)(sAl + base + 8*72 + 8);
            }
#pragma unroll
            for (int nt = 0; nt < 4; nt++) {
                int nb = (wn*32 + nt*8 + g)*72 + kc;
                bh[nt][0] = *(const uint32_t*)(sBh + nb);
                bh[nt][1] = *(const uint32_t*)(sBh + nb + 8);
                bl[nt][0] = *(const uint32_t*)(sBl + nb);
                bl[nt][1] = *(const uint32_t*)(sBl + nb + 8);
            }
#pragma unroll
            for (int mt = 0; mt < 4; mt++)
#pragma unroll
                for (int nt = 0; nt < 4; nt++) {
                    mma16816(acc[mt][nt], ah[mt], bh[nt]);
                    mma16816(acc[mt][nt], al[mt], bh[nt]);
                    mma16816(acc[mt][nt], ah[mt], bl[nt]);
                }
        }
    }
    // -------- epilogue --------
    __syncthreads();
    float* stage = (float*)smem;          // [n 64][m 256] at stride 261 (odd)
#pragma unroll
    for (int mt = 0; mt < 4; mt++)
#pragma unroll
        for (int nt = 0; nt < 4; nt++) {
            int m = wm*64 + mt*16 + g;
            int n = wn*32 + nt*8 + q*2;
            stage[n*261 + m]         = acc[mt][nt][0];
            stage[(n+1)*261 + m]     = acc[mt][nt][1];
            stage[n*261 + m + 8]     = acc[mt][nt][2];
            stage[(n+1)*261 + m + 8] = acc[mt][nt][3];
        }
    __syncthreads();

    if (OUTMODE == 2) {
        float* sW2 = (float*)(smem + 67072);   // 64*12 f32
        float* sB1 = sW2 + 64*12;              // 64 f32
        for (int i = tid; i < 64*12; i += 256)
            sW2[i] = __ldg(W2 + (sec*64 + i/12)*12 + (i%12));
        if (tid < 64) sB1[tid] = __ldg(bias + sec*64 + tid);
        __syncthreads();
        for (int i = tid; i < 256*12; i += 256) {
            int tl = i / 12, o = i % 12;
            float s = 0.f;
#pragma unroll 8
            for (int cl = 0; cl < 64; cl++) {
                float v = stage[cl*261 + tl] + sB1[cl];
                v = v > 0.f ? v : 0.f;
                s += v * sW2[cl*12 + o];
            }
            part[((size_t)sec*BT + bz*TDIM + t0 + tl)*12 + o] = s;
        }
        return;
    }

    if (OUTMODE == 3) {
        size_t abase = (((size_t)bz*CHOUT + sec)*544 + 16 + t0)*64;
        for (int i = tid; i < 4096; i += 256) {
            int c4 = (i & 15) * 4, tl = i >> 4;
            float v[4];
#pragma unroll
            for (int j = 0; j < 4; j++)
                v[j] = gelu1(stage[(c4 + j)*261 + tl] + __ldg(bias + sec*64 + c4 + j));
            uint2 uh, ul;
            pack4(v, uh, ul);
            *(uint2*)(oAh + abase + (size_t)tl*64 + c4) = uh;
            *(uint2*)(oAl + abase + (size_t)tl*64 + c4) = ul;
        }
        return;
    }
    // OUTMODE 1 / 4: add bias (+res) in-place first (coalesced res reads)
    for (int i = tid; i < 64*256; i += 256) {
        int cl = i >> 8, tl = i & 255;
        int co = sec*64 + cl;
        float v = stage[cl*261 + tl] + __ldg(bias + co);
        if (RES) v += __ldg(res + ((size_t)bz*COUT + co)*TDIM + t0 + tl);
        stage[cl*261 + tl] = v;
    }
    __syncthreads();
    if (OUTMODE == 1 && bz < 256) {
        int slice = (int)(bz >> 7), b = (int)(bz & 127);
        float* dst = outt + (((size_t)slice*BT) + (size_t)b*TDIM + t0)*DOUT + sec*64;
        for (int i = tid; i < 256*64; i += 256) {
            int tl = i >> 6, cl = i & 63;
            dst[(size_t)tl*DOUT + cl] = stage[cl*261 + tl];
        }
    } else if (OUTMODE == 1) {
        // slice 2 -> raw A h/l for the dense head
        size_t abase = ((((size_t)bz - 256)*CHOUT + sec)*544 + 16 + t0)*64;
        for (int i = tid; i < 4096; i += 256) {
            int c4 = (i & 15) * 4, tl = i >> 4;
            float v[4];
#pragma unroll
            for (int j = 0; j < 4; j++) v[j] = stage[(c4 + j)*261 + tl];
            uint2 uh, ul;
            pack4(v, uh, ul);
            *(uint2*)(oAh + abase + (size_t)tl*64 + c4) = uh;
            *(uint2*)(oAl + abase + (size_t)tl*64 + c4) = ul;
        }
    } else {
        // OUTMODE 4: raw A (oAh2/l2) + gelu A (oAh/l)
        size_t abase = (((size_t)bz*CHOUT + sec)*544 + 16 + t0)*64;
        for (int i = tid; i < 4096; i += 256) {
            int c4 = (i & 15) * 4, tl = i >> 4;
            float v[4], gv[4];
#pragma unroll
            for (int j = 0; j < 4; j++) {
                v[j] = stage[(c4 + j)*261 + tl];
                gv[j] = gelu1(v[j]);
            }
            uint2 uh, ul, gh, gl;
            pack4(v, uh, ul);
            pack4(gv, gh, gl);
            *(uint2*)(oAh2 + abase + (size_t)tl*64 + c4) = uh;
            *(uint2*)(oAl2 + abase + (size_t)tl*64 + c4) = ul;
            *(uint2*)(oAh + abase + (size_t)tl*64 + c4) = gh;
            *(uint2*)(oAl + abase + (size_t)tl*64 + c4) = gl;
        }
    }
}

// ---- reduce 20 dense partials + b2 -> interp ----
__global__ void reduce_kernel(const float* __restrict__ part,
                              const float* __restrict__ b2,
                              float* __restrict__ interp) {
    int i = blockIdx.x * 256 + threadIdx.x;
    if (i >= BT * DIN) return;
    float s = b2[i % 12];
#pragma unroll
    for (int sec = 0; sec < 20; sec++) s += part[(size_t)sec*BT*DIN + i];
    interp[i] = s;
}

// ---- finale: outputs + masks + passthrough (GRU provably dead: mask1==1) ---
__global__ void finale_kernel(const float* __restrict__ interp,
                              const float* __restrict__ M12, const float* __restrict__ c12,
                              const float* __restrict__ x1, const float* __restrict__ x2,
                              float* __restrict__ o1, float* __restrict__ o2,
                              float* __restrict__ om1, float* __restrict__ om2,
                              float* __restrict__ ox1, float* __restrict__ ox2) {
    int r = blockIdx.x * blockDim.x + threadIdx.x;
    if (r >= BT) return;
    float xv[12];
#pragma unroll
    for (int i = 0; i < 12; i++) xv[i] = interp[r * 12 + i];
#pragma unroll
    for (int j = 0; j < 12; j++) {
        float s = c12[j];
#pragma unroll
        for (int i = 0; i < 12; i++) s += xv[i] * M12[i * 12 + j];
        o1[r * 12 + j] = s;
        o2[r * 12 + j] = s;
    }
#pragma unroll
    for (int j = 0; j < 12; j++) {
        float a = x1[r * 12 + j], b = x2[r * 12 + j];
        om1[r * 12 + j] = (a != 0.f) ? 1.f : 0.f;
        om2[r * 12 + j] = (b != 0.f) ? 1.f : 0.f;
        ox1[r * 12 + j] = a;
        ox2[r * 12 + j] = b;
    }
}

// ---------------- host ----------------
#define SMEM_MMA 111744

extern "C" void kernel_launch(void* const* d_in, const int* in_sizes, int n_in,
                              void* d_out, int out_size) {
    const float* x1 = (const float*)d_in[0];
    const float* x2 = (const float*)d_in[1];
    const float* X1 = (const float*)d_in[2];
    const float* X2 = (const float*)d_in[3];
    const float* w_in = (const float*)d_in[5];
    const float* b_in = (const float*)d_in[6];
    const float* c0_1_w = (const float*)d_in[7];
    const float* c0_1_b = (const float*)d_in[8];
    const float* c0_2_w = (const float*)d_in[9];
    const float* c0_2_b = (const float*)d_in[10];
    const float* c1_p_w = (const float*)d_in[11];
    const float* c1_p_b = (const float*)d_in[12];
    const float* c1_1_w = (const float*)d_in[13];
    const float* c1_1_b = (const float*)d_in[14];
    const float* c1_2_w = (const float*)d_in[15];
    const float* c1_2_b = (const float*)d_in[16];
    const float* ih_dense_w = (const float*)d_in[17];
    const float* ih_dense_b = (const float*)d_in[18];
    const float* ih_proj_w = (const float*)d_in[19];
    const float* ih_proj_b = (const float*)d_in[20];
    const float* fc_w = (const float*)d_in[21];
    const float* fc_b = (const float*)d_in[22];
    const float* fcr_w = (const float*)d_in[29];
    const float* fcr_b = (const float*)d_in[30];

    float *b64a, *interp, *part, *M12, *c12, *bias12;
    __nv_bfloat16 *Aga_h, *Aga_l, *Agb_h, *Agb_l, *Ang_h, *Ang_l;
    __nv_bfloat16 *A320h, *A320l, *A320h2, *A320l2, *img;
    cudaGetSymbolAddress((void**)&b64a, g_b64_a);
    cudaGetSymbolAddress((void**)&interp, g_interp);
    cudaGetSymbolAddress((void**)&part, g_part);
    cudaGetSymbolAddress((void**)&M12, g_M12);
    cudaGetSymbolAddress((void**)&c12, g_c12);
    cudaGetSymbolAddress((void**)&bias12, g_bias12);
    cudaGetSymbolAddress((void**)&Aga_h, g_Aga_h);
    cudaGetSymbolAddress((void**)&Aga_l, g_Aga_l);
    cudaGetSymbolAddress((void**)&Agb_h, g_Agb_h);
    cudaGetSymbolAddress((void**)&Agb_l, g_Agb_l);
    cudaGetSymbolAddress((void**)&Ang_h, g_Ang_h);
    cudaGetSymbolAddress((void**)&Ang_l, g_Ang_l);
    cudaGetSymbolAddress((void**)&A320h, g_A320h);
    cudaGetSymbolAddress((void**)&A320l, g_A320l);
    cudaGetSymbolAddress((void**)&A320h2, g_A320h2);
    cudaGetSymbolAddress((void**)&A320l2, g_A320l2);
    cudaGetSymbolAddress((void**)&img, g_img);

    cudaFuncSetAttribute(conv_mma_kernel<64,64,3,1,false,3,false>,
                         cudaFuncAttributeMaxDynamicSharedMemorySize, SMEM_MMA);
    cudaFuncSetAttribute(conv_mma_kernel<64,64,3,1,true,4,false>,
                         cudaFuncAttributeMaxDynamicSharedMemorySize, SMEM_MMA);
    cudaFuncSetAttribute(conv_mma_kernel<64,320,3,2,false,3,false>,
                         cudaFuncAttributeMaxDynamicSharedMemorySize, SMEM_MMA);
    cudaFuncSetAttribute(conv_mma_kernel<320,320,3,2,false,1,true>,
                         cudaFuncAttributeMaxDynamicSharedMemorySize, SMEM_MMA);
    cudaFuncSetAttribute(conv_mma_kernel<320,1280,1,1,false,2,false>,
                         cudaFuncAttributeMaxDynamicSharedMemorySize, SMEM_MMA);

    float* out = (float*)d_out;
    float* o_o1  = out + 2 * (size_t)BT * DOUT;
    float* o_o2  = o_o1 + (size_t)BT * DIN;
    float* o_m1  = o_o2 + (size_t)BT * DIN;
    float* o_m2  = o_m1 + (size_t)BT * DIN;
    float* o_x1  = o_m2 + (size_t)BT * DIN;
    float* o_x2  = o_x1 + (size_t)BT * DIN;

    setup_kernel<<<3216, 256>>>(c0_1_w, c0_2_w, c1_p_w, c1_1_w, c1_2_w, ih_dense_w,
                                fc_w, fc_b, fcr_w, fcr_b, c1_2_b, c1_p_b,
                                M12, c12, bias12);
    // proj -> f32 residual + gelu A (conv01 input)
    proj_in3_kernel<<<dim3(4, NB), 128>>>(X1, X2, x1, w_in, b_in, b64a, Aga_h, Aga_l);

    // block0
    conv_mma_kernel<64,64,3,1,false,3,false><<<dim3(2,1,NB), 256, SMEM_MMA>>>(
        Aga_h, Aga_l, nullptr, nullptr, img, c0_1_b, nullptr, nullptr, nullptr, nullptr,
        Agb_h, Agb_l, nullptr, nullptr);
    conv_mma_kernel<64,64,3,1,true,4,false><<<dim3(2,1,NB), 256, SMEM_MMA>>>(
        Agb_h, Agb_l, nullptr, nullptr, img + (size_t)3*9216, c0_2_b, b64a,
        nullptr, nullptr, nullptr, Aga_h, Aga_l, Ang_h, Ang_l);
    // block1: conv11 (gelu out), then conv12 with fused 1x1 projection residual
    conv_mma_kernel<64,320,3,2,false,3,false><<<dim3(2,5,NB), 256, SMEM_MMA>>>(
        Aga_h, Aga_l, nullptr, nullptr, img + (size_t)86*9216, c1_1_b, nullptr,
        nullptr, nullptr, nullptr, A320h, A320l, nullptr, nullptr);
    conv_mma_kernel<320,320,3,2,false,1,true><<<dim3(2,5,NB), 256, SMEM_MMA>>>(
        A320h, A320l, Ang_h, Ang_l, img + (size_t)6*9216, bias12, nullptr,
        out, nullptr, nullptr, A320h2, A320l2, nullptr, nullptr);
    // dense head on slice 2 (dense2 fused into epilogue -> partials)
    conv_mma_kernel<320,1280,1,1,false,2,false><<<dim3(2,20,BB), 256, SMEM_MMA>>>(
        A320h2, A320l2, nullptr, nullptr, img + (size_t)101*9216, ih_dense_b, nullptr,
        nullptr, ih_proj_w, part, nullptr, nullptr, nullptr, nullptr);
    reduce_kernel<<<(BT*DIN + 255)/256, 256>>>(part, ih_proj_b, interp);
    finale_kernel<<<(BT + 127) / 128, 128>>>(interp, M12, c12, x1, x2,
                                             o_o1, o_o2, o_m1, o_m2, o_x1, o_x2);
}

// round 16
// speedup vs baseline: 2.1275x; 1.0297x over previous
#include <cuda_runtime.h>
#include <cuda_bf16.h>
#include <math.h>
#include <stdint.h>

#define BB 128
#define NB 384
#define TDIM 512
#define DIN 12
#define HH 64
#define DOUT 320
#define BT (BB*TDIM)

// ---------------- static scratch ----------------
__device__ float g_b64f[(size_t)NB*TDIM*HH];      // proj f32 residual, t-major
__device__ float g_part[(size_t)20*BT*DIN];
__device__ float g_M12[144];
__device__ float g_c12[12];
__device__ float g_bias12[DOUT];                  // c1_2_b + c1_p_b
// A-format activations: [bz][ch][544 rows (16 pad | 512 | 16 pad)][64 ci] bf16
// pads never written -> stay zero from static init
__device__ __align__(16) __nv_bfloat16 g_Aga_h[(size_t)NB*544*64];
__device__ __align__(16) __nv_bfloat16 g_Aga_l[(size_t)NB*544*64];
__device__ __align__(16) __nv_bfloat16 g_Agb_h[(size_t)NB*544*64];
__device__ __align__(16) __nv_bfloat16 g_Agb_l[(size_t)NB*544*64];
__device__ __align__(16) __nv_bfloat16 g_Ang_h[(size_t)NB*544*64];
__device__ __align__(16) __nv_bfloat16 g_Ang_l[(size_t)NB*544*64];
__device__ __align__(16) __nv_bfloat16 g_A320h[(size_t)NB*5*544*64];
__device__ __align__(16) __nv_bfloat16 g_A320l[(size_t)NB*5*544*64];
__device__ __align__(16) __nv_bfloat16 g_A320h2[(size_t)BB*5*544*64];
__device__ __align__(16) __nv_bfloat16 g_A320l2[(size_t)BB*5*544*64];
// weight images: 201 blocks of [hl 2][n 64][k 72] bf16 (9216 elems each)
// layout: [0,3) conv01 | [3,6) conv02 | [6,86) conv12+c1p (sec*16+it, it=15 is
// c1p) | [86,101) conv11 | [101,201) dense
__device__ __align__(16) __nv_bfloat16 g_img[(size_t)201*9216];

// ---------------- helpers ----------------
__device__ __forceinline__ uint32_t s2u(const void* p) {
    uint32_t a;
    asm("{ .reg .u64 t; cvta.to.shared.u64 t, %1; cvt.u32.u64 %0, t; }" : "=r"(a) : "l"(p));
    return a;
}
__device__ __forceinline__ void cp16(uint32_t d, const void* s) {
    asm volatile("cp.async.cg.shared.global [%0], [%1], 16;" :: "r"(d), "l"(s));
}
#define CP_COMMIT() asm volatile("cp.async.commit_group;" ::: "memory")
#define CP_WAIT1()  asm volatile("cp.async.wait_group 1;" ::: "memory")
#define CP_WAIT0()  asm volatile("cp.async.wait_group 0;" ::: "memory")

__device__ __forceinline__ void mma16816(float* c, const uint32_t* a, const uint32_t* b) {
    asm volatile(
        "mma.sync.aligned.m16n8k16.row.col.f32.bf16.bf16.f32 "
        "{%0,%1,%2,%3}, {%4,%5,%6,%7}, {%8,%9}, {%0,%1,%2,%3};"
        : "+f"(c[0]), "+f"(c[1]), "+f"(c[2]), "+f"(c[3])
        : "r"(a[0]), "r"(a[1]), "r"(a[2]), "r"(a[3]), "r"(b[0]), "r"(b[1]));
}
__device__ __forceinline__ float gelu1(float x) {
    return 0.5f * x * (1.0f + erff(x * 0.7071067811865476f));
}
__device__ __forceinline__ void pack4(const float* v, uint2& uh, uint2& ul) {
    __nv_bfloat16 h[4], l[4];
#pragma unroll
    for (int j = 0; j < 4; j++) {
        h[j] = __float2bfloat16(v[j]);
        l[j] = __float2bfloat16(v[j] - __bfloat162float(h[j]));
    }
    uh = *(const uint2*)h;
    ul = *(const uint2*)l;
}

// ---------------- setup: weight images (hi/lo bf16) + M12 + bias12 ----------
__global__ void setup_kernel(
    const float* __restrict__ c01w, const float* __restrict__ c02w,
    const float* __restrict__ c1pw, const float* __restrict__ c11w,
    const float* __restrict__ c12w, const float* __restrict__ dw,
    const float* __restrict__ fc_w, const float* __restrict__ fc_b,
    const float* __restrict__ fcr_w, const float* __restrict__ fcr_b,
    const float* __restrict__ c12b, const float* __restrict__ c1pb,
    float* __restrict__ M12, float* __restrict__ c12, float* __restrict__ bias12)
{
    const int TOT = 201 * 4096;
    int stride = gridDim.x * 256;
    for (int i = blockIdx.x*256 + threadIdx.x; i < TOT; i += stride) {
        int blk = i >> 12, e = i & 4095;
        int n = e >> 6, k = e & 63;
        float w;
        if (blk < 3) {
            w = c01w[(n*64 + k)*3 + blk];
        } else if (blk < 6) {
            w = c02w[(n*64 + k)*3 + (blk - 3)];
        } else if (blk < 86) {
            int r = blk - 6, sec = r >> 4, it = r & 15;
            if (it < 15) {
                int ch = it / 3, tap = it % 3;
                w = c12w[((sec*64 + n)*320 + ch*64 + k)*3 + tap];
            } else {
                w = c1pw[(sec*64 + n)*64 + k];
            }
        } else if (blk < 101) {
            int r = blk - 86, sec = r/3, tap = r%3;
            w = c11w[((sec*64 + n)*64 + k)*3 + tap];
        } else {
            int r = blk - 101, s = r/5, ch = r%5;
            w = dw[(ch*64 + k)*1280 + s*64 + n];
        }
        size_t base = (size_t)blk * 9216;
        uint32_t idx = (uint32_t)n * 72 + (uint32_t)k;
        __nv_bfloat16 h = __float2bfloat16(w);
        g_img[base + idx] = h;
        g_img[base + 4608 + idx] = __float2bfloat16(w - __bfloat162float(h));
    }
    if (blockIdx.x == 0) {
        int tid = threadIdx.x;
        if (tid < 144) {
            int a = tid / 12, bj = tid % 12;
            float s = 0.f;
            for (int k = 0; k < DOUT; k++) s += fc_w[a*DOUT + k] * fcr_w[k*12 + bj];
            M12[tid] = s;
        } else if (tid < 156) {
            int bj = tid - 144;
            float s = fcr_b[bj];
            for (int k = 0; k < DOUT; k++) s += fc_b[k] * fcr_w[k*12 + bj];
            c12[bj] = s;
        }
    }
    if (blockIdx.x == 1) {
        for (int c = threadIdx.x; c < DOUT; c += 256)
            bias12[c] = c12b[c] + c1pb[c];
    }
}

// ---------------- tensor-core conv via mma.sync (split bf16, 3-pass) --------
// CTA tile M=256 x N=64; 8 warps (4M x 2N), warp tile 64x32.
// PROJ: build A from the 12->64 input projection in-kernel (no gmem A read);
//       also writes the f32 residual t-major to pres.
// RC:   append one extra iteration (A = gA2, shift 0) accumulating the 1x1
//       projection residual directly into acc.
// OUTMODE: 1 = conv12: slices 0/1 transposed f32 to d_out; slice 2 raw A h/l
//          2 = dense head (relu + W2 partial to g_part)
//          3 = gelu A h/l (+bias)
//          4 = conv02: raw A h/l AND gelu A h/l, +bias + t-major res
template<int CIN, int COUT, int TAPS, int DIL, bool RES, int OUTMODE, bool RC, bool PROJ>
__global__ __launch_bounds__(256, 2) void conv_mma_kernel(
    const __nv_bfloat16* __restrict__ gAh, const __nv_bfloat16* __restrict__ gAl,
    const __nv_bfloat16* __restrict__ gA2h, const __nv_bfloat16* __restrict__ gA2l,
    const __nv_bfloat16* __restrict__ img,
    const float* __restrict__ bias, const float* __restrict__ res,
    float* __restrict__ outt,
    const float* __restrict__ W2, float* __restrict__ part,
    __nv_bfloat16* __restrict__ oAh, __nv_bfloat16* __restrict__ oAl,
    __nv_bfloat16* __restrict__ oAh2, __nv_bfloat16* __restrict__ oAl2,
    const float* __restrict__ pX1, const float* __restrict__ pX2,
    const float* __restrict__ px1, const float* __restrict__ pw,
    const float* __restrict__ pbi, float* __restrict__ pres)
{
    constexpr int CHUNKS = CIN / 64;
    constexpr int CHOUT = COUT / 64;
    constexpr int NIT = CHUNKS * TAPS + (RC ? 1 : 0);
    extern __shared__ __align__(16) char smem[];
    uint32_t sb = s2u(smem);

    int tid = threadIdx.x, lane = tid & 31, wid = tid >> 5;
    int g = lane >> 2, q = lane & 3;
    int wm = wid >> 1, wn = wid & 1;
    size_t bz = blockIdx.z;
    int t0 = blockIdx.x * 256, sec = blockIdx.y;

    float acc[4][4][4];
#pragma unroll
    for (int a = 0; a < 4; a++)
#pragma unroll
        for (int b = 0; b < 4; b++)
#pragma unroll
            for (int c = 0; c < 4; c++) acc[a][b][c] = 0.f;

    // A: [0, 74880) single buffer (hi 37440 | lo 37440), 260 rows x 72 stride
    // B: [74880, 111744) two buffers of 18432
    auto loadA = [&](const __nv_bfloat16* srcH, const __nv_bfloat16* srcL,
                     size_t rowbase) {
        for (int i = tid; i < 4160; i += 256) {
            int hl = (i >= 2080) ? 1 : 0;
            int rr = i - hl * 2080;
            int r = rr >> 3, c = rr & 7;
            const __nv_bfloat16* gsrc = (hl ? srcL : srcH) + (rowbase + r) * 64 + c * 8;
            cp16(sb + hl*37440 + r*144 + c*16, gsrc);
        }
    };
    auto loadB = [&](int it2, int slot) {
        const char* gsrc = (const char*)(img + ((size_t)sec * NIT + it2) * 9216);
        for (int i = tid; i < 1152; i += 256)
            cp16(sb + 74880 + slot*18432 + i*16, gsrc + i*16);
    };

    if (PROJ) {
        // build A (gelu of 12->64 projection) directly in smem; write f32 res
        int b = (int)(bz & 127);
        const float* x = (bz < 128) ? pX1 : (bz < 256) ? pX2 : px1;
        __nv_bfloat16* wAh = (__nv_bfloat16*)smem;
        __nv_bfloat16* wAl = wAh + 18720;
        for (int i = tid; i < 260*64; i += 256) {
            int r = i >> 6, c = i & 63;
            int t = t0 + r - 2;
            float s = 0.f;
            if (t >= 0 && t < TDIM) {
                s = pbi[c];
                const float* xr = x + ((size_t)b*TDIM + t)*DIN;
#pragma unroll
                for (int j = 0; j < DIN; j++) s += xr[j] * pw[j*64 + c];
                pres[((size_t)bz*TDIM + t)*64 + c] = s;
            }
            float gv = gelu1(s);
            __nv_bfloat16 h = __float2bfloat16(gv);
            wAh[r*72 + c] = h;
            wAl[r*72 + c] = __float2bfloat16(gv - __bfloat162float(h));
        }
    }
    loadB(0, 0);
    CP_COMMIT();

    for (int it = 0; it < NIT; it++) {
        int shift;
        bool nc;
        bool rcit = RC && (it == CHUNKS * TAPS);
        if (rcit) { shift = 0; nc = true; }
        else {
            int tap = it % TAPS;
            shift = (tap - (TAPS - 1) / 2) * DIL;
            nc = (tap == 0) && !PROJ;
        }
        __syncthreads();     // prior compute done: A buffer / B slot safe
        if (nc) {
            if (rcit) loadA(gA2h, gA2l, (size_t)bz * 544 + (16 + t0 - 2));
            else      loadA(gAh, gAl, ((size_t)bz * CHUNKS + it / TAPS) * 544 + (16 + t0 - 2));
            CP_COMMIT();
        }
        if (it + 1 < NIT) {
            loadB(it + 1, (it + 1) & 1);
            CP_COMMIT();
            CP_WAIT1();      // A (if any) + B(it) complete; B(it+1) in flight
        } else {
            CP_WAIT0();
        }
        __syncthreads();
        const __nv_bfloat16* sAh = (const __nv_bfloat16*)smem;
        const __nv_bfloat16* sAl = sAh + 18720;
        const __nv_bfloat16* sBh = (const __nv_bfloat16*)(smem + 74880 + (it & 1)*18432);
        const __nv_bfloat16* sBl = sBh + 4608;
        int rb = 2 + shift + wm*64 + g;
#pragma unroll
        for (int ks = 0; ks < 4; ks++) {
            int kc = ks*16 + q*2;
            uint32_t ah[4][4], al[4][4], bh[4][2], bl[4][2];
#pragma unroll
            for (int mt = 0; mt < 4; mt++) {
                int base = (rb + mt*16)*72 + kc;
                ah[mt][0] = *(const uint32_t*)(sAh + base);
                ah[mt][1] = *(const uint32_t*)(sAh + base + 8*72);
                ah[mt][2] = *(const uint32_t*)(sAh + base + 8);
                ah[mt][3] = *(const uint32_t*)(sAh + base + 8*72 + 8);
                al[mt][0] = *(const uint32_t*)(sAl + base);
                al[mt][1] = *(const uint32_t*)(sAl + base + 8*72);
                al[mt][2] = *(const uint32_t*)(sAl + base + 8);
                al[mt][3] = *(const uint32_t*)(sAl + base + 8*72 + 8);
            }
#pragma unroll
            for (int nt = 0; nt < 4; nt++) {
                int nb = (wn*32 + nt*8 + g)*72 + kc;
                bh[nt][0] = *(const uint32_t*)(sBh + nb);
                bh[nt][1] = *(const uint32_t*)(sBh + nb + 8);
                bl[nt][0] = *(const uint32_t*)(sBl + nb);
                bl[nt][1] = *(const uint32_t*)(sBl + nb + 8);
            }
#pragma unroll
            for (int mt = 0; mt < 4; mt++)
#pragma unroll
                for (int nt = 0; nt < 4; nt++) {
                    mma16816(acc[mt][nt], ah[mt], bh[nt]);
                    mma16816(acc[mt][nt], al[mt], bh[nt]);
                    mma16816(acc[mt][nt], ah[mt], bl[nt]);
                }
        }
    }
    // -------- epilogue --------
    __syncthreads();
    float* stage = (float*)smem;          // [n 64][m 256] at stride 261 (odd)
#pragma unroll
    for (int mt = 0; mt < 4; mt++)
#pragma unroll
        for (int nt = 0; nt < 4; nt++) {
            int m = wm*64 + mt*16 + g;
            int n = wn*32 + nt*8 + q*2;
            stage[n*261 + m]         = acc[mt][nt][0];
            stage[(n+1)*261 + m]     = acc[mt][nt][1];
            stage[n*261 + m + 8]     = acc[mt][nt][2];
            stage[(n+1)*261 + m + 8] = acc[mt][nt][3];
        }
    __syncthreads();

    if (OUTMODE == 2) {
        float* sW2 = (float*)(smem + 67072);   // 64*12 f32
        float* sB1 = sW2 + 64*12;              // 64 f32
        for (int i = tid; i < 64*12; i += 256)
            sW2[i] = __ldg(W2 + (sec*64 + i/12)*12 + (i%12));
        if (tid < 64) sB1[tid] = __ldg(bias + sec*64 + tid);
        __syncthreads();
        for (int i = tid; i < 256*12; i += 256) {
            int tl = i / 12, o = i % 12;
            float s = 0.f;
#pragma unroll 8
            for (int cl = 0; cl < 64; cl++) {
                float v = stage[cl*261 + tl] + sB1[cl];
                v = v > 0.f ? v : 0.f;
                s += v * sW2[cl*12 + o];
            }
            part[((size_t)sec*BT + bz*TDIM + t0 + tl)*12 + o] = s;
        }
        return;
    }
    if (OUTMODE == 3) {
        size_t abase = (((size_t)bz*CHOUT + sec)*544 + 16 + t0)*64;
        for (int i = tid; i < 4096; i += 256) {
            int c4 = (i & 15) * 4, tl = i >> 4;
            float v[4];
#pragma unroll
            for (int j = 0; j < 4; j++)
                v[j] = gelu1(stage[(c4 + j)*261 + tl] + __ldg(bias + sec*64 + c4 + j));
            uint2 uh, ul;
            pack4(v, uh, ul);
            *(uint2*)(oAh + abase + (size_t)tl*64 + c4) = uh;
            *(uint2*)(oAl + abase + (size_t)tl*64 + c4) = ul;
        }
        return;
    }
    if (OUTMODE == 1) {
        if (bz < 256) {
            int slice = (int)(bz >> 7), b = (int)(bz & 127);
            float* dst = outt + (((size_t)slice*BT) + (size_t)b*TDIM + t0)*DOUT + sec*64;
            for (int i = tid; i < 256*64; i += 256) {
                int tl = i >> 6, cl = i & 63;
                dst[(size_t)tl*DOUT + cl] = stage[cl*261 + tl] + __ldg(bias + sec*64 + cl);
            }
        } else {
            size_t abase = ((((size_t)bz - 256)*CHOUT + sec)*544 + 16 + t0)*64;
            for (int i = tid; i < 4096; i += 256) {
                int c4 = (i & 15) * 4, tl = i >> 4;
                float v[4];
#pragma unroll
                for (int j = 0; j < 4; j++)
                    v[j] = stage[(c4 + j)*261 + tl] + __ldg(bias + sec*64 + c4 + j);
                uint2 uh, ul;
                pack4(v, uh, ul);
                *(uint2*)(oAh + abase + (size_t)tl*64 + c4) = uh;
                *(uint2*)(oAl + abase + (size_t)tl*64 + c4) = ul;
            }
        }
        return;
    }
    // OUTMODE 4: single pass; res is t-major f32 [bz][t][64]
    {
        size_t abase = (((size_t)bz*CHOUT + sec)*544 + 16 + t0)*64;
        for (int i = tid; i < 4096; i += 256) {
            int c4 = (i & 15) * 4, tl = i >> 4;
            float4 rv = *(const float4*)&res[((size_t)bz*TDIM + t0 + tl)*64 + c4];
            float v[4], gv[4];
            v[0] = stage[(c4+0)*261 + tl] + __ldg(bias + c4+0) + rv.x;
            v[1] = stage[(c4+1)*261 + tl] + __ldg(bias + c4+1) + rv.y;
            v[2] = stage[(c4+2)*261 + tl] + __ldg(bias + c4+2) + rv.z;
            v[3] = stage[(c4+3)*261 + tl] + __ldg(bias + c4+3) + rv.w;
#pragma unroll
            for (int j = 0; j < 4; j++) gv[j] = gelu1(v[j]);
            uint2 uh, ul, gh, gl;
            pack4(v, uh, ul);
            pack4(gv, gh, gl);
            *(uint2*)(oAh2 + abase + (size_t)tl*64 + c4) = uh;
            *(uint2*)(oAl2 + abase + (size_t)tl*64 + c4) = ul;
            *(uint2*)(oAh + abase + (size_t)tl*64 + c4) = gh;
            *(uint2*)(oAl + abase + (size_t)tl*64 + c4) = gl;
        }
    }
}

// ---- finale: reduce 20 dense partials + outputs + masks + passthrough ------
// (GRU provably dead: mask1 == 1)
__global__ void finale_kernel(const float* __restrict__ part,
                              const float* __restrict__ b2,
                              const float* __restrict__ M12, const float* __restrict__ c12,
                              const float* __restrict__ x1, const float* __restrict__ x2,
                              float* __restrict__ o1, float* __restrict__ o2,
                              float* __restrict__ om1, float* __restrict__ om2,
                              float* __restrict__ ox1, float* __restrict__ ox2) {
    int r = blockIdx.x * blockDim.x + threadIdx.x;
    if (r >= BT) return;
    float xv[12];
#pragma unroll
    for (int i = 0; i < 12; i++) {
        float s = b2[i];
#pragma unroll
        for (int sec = 0; sec < 20; sec++) s += part[(size_t)sec*BT*DIN + r*12 + i];
        xv[i] = s;
    }
#pragma unroll
    for (int j = 0; j < 12; j++) {
        float s = c12[j];
#pragma unroll
        for (int i = 0; i < 12; i++) s += xv[i] * M12[i * 12 + j];
        o1[r * 12 + j] = s;
        o2[r * 12 + j] = s;
    }
#pragma unroll
    for (int j = 0; j < 12; j++) {
        float a = x1[r * 12 + j], b = x2[r * 12 + j];
        om1[r * 12 + j] = (a != 0.f) ? 1.f : 0.f;
        om2[r * 12 + j] = (b != 0.f) ? 1.f : 0.f;
        ox1[r * 12 + j] = a;
        ox2[r * 12 + j] = b;
    }
}

// ---------------- host ----------------
#define SMEM_MMA 111744

extern "C" void kernel_launch(void* const* d_in, const int* in_sizes, int n_in,
                              void* d_out, int out_size) {
    const float* x1 = (const float*)d_in[0];
    const float* x2 = (const float*)d_in[1];
    const float* X1 = (const float*)d_in[2];
    const float* X2 = (const float*)d_in[3];
    const float* w_in = (const float*)d_in[5];
    const float* b_in = (const float*)d_in[6];
    const float* c0_1_w = (const float*)d_in[7];
    const float* c0_1_b = (const float*)d_in[8];
    const float* c0_2_w = (const float*)d_in[9];
    const float* c0_2_b = (const float*)d_in[10];
    const float* c1_p_w = (const float*)d_in[11];
    const float* c1_p_b = (const float*)d_in[12];
    const float* c1_1_w = (const float*)d_in[13];
    const float* c1_1_b = (const float*)d_in[14];
    const float* c1_2_w = (const float*)d_in[15];
    const float* c1_2_b = (const float*)d_in[16];
    const float* ih_dense_w = (const float*)d_in[17];
    const float* ih_dense_b = (const float*)d_in[18];
    const float* ih_proj_w = (const float*)d_in[19];
    const float* ih_proj_b = (const float*)d_in[20];
    const float* fc_w = (const float*)d_in[21];
    const float* fc_b = (const float*)d_in[22];
    const float* fcr_w = (const float*)d_in[29];
    const float* fcr_b = (const float*)d_in[30];

    float *b64f, *part, *M12, *c12, *bias12;
    __nv_bfloat16 *Aga_h, *Aga_l, *Agb_h, *Agb_l, *Ang_h, *Ang_l;
    __nv_bfloat16 *A320h, *A320l, *A320h2, *A320l2, *img;
    cudaGetSymbolAddress((void**)&b64f, g_b64f);
    cudaGetSymbolAddress((void**)&part, g_part);
    cudaGetSymbolAddress((void**)&M12, g_M12);
    cudaGetSymbolAddress((void**)&c12, g_c12);
    cudaGetSymbolAddress((void**)&bias12, g_bias12);
    cudaGetSymbolAddress((void**)&Aga_h, g_Aga_h);
    cudaGetSymbolAddress((void**)&Aga_l, g_Aga_l);
    cudaGetSymbolAddress((void**)&Agb_h, g_Agb_h);
    cudaGetSymbolAddress((void**)&Agb_l, g_Agb_l);
    cudaGetSymbolAddress((void**)&Ang_h, g_Ang_h);
    cudaGetSymbolAddress((void**)&Ang_l, g_Ang_l);
    cudaGetSymbolAddress((void**)&A320h, g_A320h);
    cudaGetSymbolAddress((void**)&A320l, g_A320l);
    cudaGetSymbolAddress((void**)&A320h2, g_A320h2);
    cudaGetSymbolAddress((void**)&A320l2, g_A320l2);
    cudaGetSymbolAddress((void**)&img, g_img);

    cudaFuncSetAttribute(conv_mma_kernel<64,64,3,1,false,3,false,true>,
                         cudaFuncAttributeMaxDynamicSharedMemorySize, SMEM_MMA);
    cudaFuncSetAttribute(conv_mma_kernel<64,64,3,1,true,4,false,false>,
                         cudaFuncAttributeMaxDynamicSharedMemorySize, SMEM_MMA);
    cudaFuncSetAttribute(conv_mma_kernel<64,320,3,2,false,3,false,false>,
                         cudaFuncAttributeMaxDynamicSharedMemorySize, SMEM_MMA);
    cudaFuncSetAttribute(conv_mma_kernel<320,320,3,2,false,1,true,false>,
                         cudaFuncAttributeMaxDynamicSharedMemorySize, SMEM_MMA);
    cudaFuncSetAttribute(conv_mma_kernel<320,1280,1,1,false,2,false,false>,
                         cudaFuncAttributeMaxDynamicSharedMemorySize, SMEM_MMA);

    float* out = (float*)d_out;
    float* o_o1  = out + 2 * (size_t)BT * DOUT;
    float* o_o2  = o_o1 + (size_t)BT * DIN;
    float* o_m1  = o_o2 + (size_t)BT * DIN;
    float* o_m2  = o_m1 + (size_t)BT * DIN;
    float* o_x1  = o_m2 + (size_t)BT * DIN;
    float* o_x2  = o_x1 + (size_t)BT * DIN;

    setup_kernel<<<3216, 256>>>(c0_1_w, c0_2_w, c1_p_w, c1_1_w, c1_2_w, ih_dense_w,
                                fc_w, fc_b, fcr_w, fcr_b, c1_2_b, c1_p_b,
                                M12, c12, bias12);

    // block0: conv01 with fused input projection (PROJ)
    conv_mma_kernel<64,64,3,1,false,3,false,true><<<dim3(2,1,NB), 256, SMEM_MMA>>>(
        nullptr, nullptr, nullptr, nullptr, img, c0_1_b, nullptr, nullptr,
        nullptr, nullptr, Agb_h, Agb_l, nullptr, nullptr,
        X1, X2, x1, w_in, b_in, b64f);
    conv_mma_kernel<64,64,3,1,true,4,false,false><<<dim3(2,1,NB), 256, SMEM_MMA>>>(
        Agb_h, Agb_l, nullptr, nullptr, img + (size_t)3*9216, c0_2_b, b64f,
        nullptr, nullptr, nullptr, Aga_h, Aga_l, Ang_h, Ang_l,
        nullptr, nullptr, nullptr, nullptr, nullptr, nullptr);
    // block1: conv11 (gelu out), then conv12 with fused 1x1 projection residual
    conv_mma_kernel<64,320,3,2,false,3,false,false><<<dim3(2,5,NB), 256, SMEM_MMA>>>(
        Aga_h, Aga_l, nullptr, nullptr, img + (size_t)86*9216, c1_1_b, nullptr,
        nullptr, nullptr, nullptr, A320h, A320l, nullptr, nullptr,
        nullptr, nullptr, nullptr, nullptr, nullptr, nullptr);
    conv_mma_kernel<320,320,3,2,false,1,true,false><<<dim3(2,5,NB), 256, SMEM_MMA>>>(
        A320h, A320l, Ang_h, Ang_l, img + (size_t)6*9216, bias12, nullptr,
        out, nullptr, nullptr, A320h2, A320l2, nullptr, nullptr,
        nullptr, nullptr, nullptr, nullptr, nullptr, nullptr);
    // dense head on slice 2 (dense2 fused into epilogue -> partials)
    conv_mma_kernel<320,1280,1,1,false,2,false,false><<<dim3(2,20,BB), 256, SMEM_MMA>>>(
        A320h2, A320l2, nullptr, nullptr, img + (size_t)101*9216, ih_dense_b, nullptr,
        nullptr, ih_proj_w, part, nullptr, nullptr, nullptr, nullptr,
        nullptr, nullptr, nullptr, nullptr, nullptr, nullptr);
    finale_kernel<<<(BT + 127) / 128, 128>>>(part, ih_proj_b, M12, c12, x1, x2,
                                             o_o1, o_o2, o_m1, o_m2, o_x1, o_x2);
}